// round 3
// baseline (speedup 1.0000x reference)
#include <cuda_runtime.h>
#include <math.h>

// Problem constants
#define B_  16
#define N_  1024
#define C_  256
#define NH_ 8
#define DH_ 32
#define M_  (B_*N_)      // 16384 rows
#define HID_ 1024

// ---------------------------------------------------------------------------
// Scratch (static __device__ arrays; no allocations allowed)
// ---------------------------------------------------------------------------
__device__ float g_y  [M_*C_];        // LN output (reused 3x)
__device__ float g_qkv[M_*3*C_];      // qkv projection
__device__ float g_tmp[M_*C_];        // attn-out / deform-out (reused)
__device__ float g_x2 [M_*C_];        // residual stream
__device__ float g_off[M_*64];        // deform offsets
__device__ float g_awl[M_*32];        // deform attention logits
__device__ float g_vp [M_*C_];        // vproj output
__device__ float g_h1 [M_*HID_];      // MLP hidden

// ---------------------------------------------------------------------------
// LayerNorm: one block per row, 256 threads (C=256)
// ---------------------------------------------------------------------------
__global__ __launch_bounds__(256) void ln_kernel(
    const float* __restrict__ in, const float* __restrict__ w,
    const float* __restrict__ b, float* __restrict__ out)
{
    __shared__ float red[8];
    int row = blockIdx.x;
    int t = threadIdx.x;
    float v = in[(size_t)row*C_ + t];
    float s = v;
    #pragma unroll
    for (int o = 16; o; o >>= 1) s += __shfl_xor_sync(0xffffffffu, s, o);
    if ((t & 31) == 0) red[t >> 5] = s;
    __syncthreads();
    float tot = 0.f;
    #pragma unroll
    for (int i = 0; i < 8; i++) tot += red[i];
    float mean = tot * (1.0f/256.0f);
    __syncthreads();
    float d = v - mean;
    s = d*d;
    #pragma unroll
    for (int o = 16; o; o >>= 1) s += __shfl_xor_sync(0xffffffffu, s, o);
    if ((t & 31) == 0) red[t >> 5] = s;
    __syncthreads();
    tot = 0.f;
    #pragma unroll
    for (int i = 0; i < 8; i++) tot += red[i];
    float rs = rsqrtf(tot*(1.0f/256.0f) + 1e-5f);
    out[(size_t)row*C_ + t] = d*rs*w[t] + b[t];
}

// ---------------------------------------------------------------------------
// GEMM: Y[M,Nout] = X[M,K] @ W[Nout,K]^T (+bias) (+gelu) (+residual)
// Tile 128x128x16, 256 threads, 8x8 micro-tile (interleaved to avoid bank
// conflicts: broadcast on A-frag, 16 distinct banks on B-frag).
// ---------------------------------------------------------------------------
#define GBM 128
#define GBN 128
#define GBK 16

__global__ __launch_bounds__(256) void gemm_kernel(
    const float* __restrict__ X, const float* __restrict__ W,
    const float* __restrict__ bias, const float* __restrict__ res,
    float* __restrict__ Y, int M, int Nout, int K, int act)
{
    __shared__ float Xs[GBK][GBM+1];
    __shared__ float Ws[GBK][GBN+1];
    int tid = threadIdx.x;
    int tx = tid & 15, ty = tid >> 4;
    int m0 = blockIdx.y * GBM;
    int n0 = blockIdx.x * GBN;

    float acc[8][8];
    #pragma unroll
    for (int i = 0; i < 8; i++)
        #pragma unroll
        for (int j = 0; j < 8; j++) acc[i][j] = 0.f;

    for (int k0 = 0; k0 < K; k0 += GBK) {
        #pragma unroll
        for (int v = 0; v < 2; v++) {
            int idx = tid + (v << 8);          // 0..511
            int mm  = idx >> 2;                // 0..127
            int kq  = (idx & 3) << 2;          // 0,4,8,12
            float4 xv = *(const float4*)(X + (size_t)(m0+mm)*K + k0 + kq);
            Xs[kq+0][mm] = xv.x; Xs[kq+1][mm] = xv.y;
            Xs[kq+2][mm] = xv.z; Xs[kq+3][mm] = xv.w;
            float4 wv = make_float4(0.f, 0.f, 0.f, 0.f);
            if (n0 + mm < Nout)
                wv = *(const float4*)(W + (size_t)(n0+mm)*K + k0 + kq);
            Ws[kq+0][mm] = wv.x; Ws[kq+1][mm] = wv.y;
            Ws[kq+2][mm] = wv.z; Ws[kq+3][mm] = wv.w;
        }
        __syncthreads();
        #pragma unroll
        for (int k = 0; k < GBK; k++) {
            float a[8], bb[8];
            #pragma unroll
            for (int i = 0; i < 8; i++) a[i]  = Xs[k][ty + 16*i];
            #pragma unroll
            for (int j = 0; j < 8; j++) bb[j] = Ws[k][tx + 16*j];
            #pragma unroll
            for (int i = 0; i < 8; i++)
                #pragma unroll
                for (int j = 0; j < 8; j++)
                    acc[i][j] = fmaf(a[i], bb[j], acc[i][j]);
        }
        __syncthreads();
    }

    #pragma unroll
    for (int i = 0; i < 8; i++) {
        int m = m0 + ty + 16*i;
        #pragma unroll
        for (int j = 0; j < 8; j++) {
            int n = n0 + tx + 16*j;
            if (n < Nout) {
                float v = acc[i][j];
                if (bias) v += bias[n];
                if (act)  v *= normcdff(v);          // exact gelu: x * Phi(x)
                if (res)  v += res[(size_t)m*Nout + n];
                Y[(size_t)m*Nout + n] = v;
            }
        }
    }
}

// ---------------------------------------------------------------------------
// Attention: per (b, h, 32-query tile). Full score row kept in smem (padded
// stride 1025 -> conflict-free). Phase1: S = QK^T (4x4 micro, col-interleaved
// so K-frag loads hit 32 distinct banks). Phase2: row softmax (warp/4 rows).
// Phase3: O = PV with 4-way key split + smem reduction.
// qkv layout: (b*N+n)*768 + s*256 + h*32 + d, s in {q,k,v}
// ---------------------------------------------------------------------------
#define AQT 32
#define AKT 128
#define ASMEM ((AQT*33 + AKT*33 + AQT*1025)*4)

__global__ __launch_bounds__(256) void attn_kernel(
    const float* __restrict__ qkv, float* __restrict__ out)
{
    extern __shared__ float sm[];
    float* q_s  = sm;                     // AQT * 33
    float* kv_s = sm + AQT*33;            // AKT * 33
    float* s_s  = kv_s + AKT*33;          // AQT * 1025

    int tid = threadIdx.x;
    int b = blockIdx.z, h = blockIdx.y;
    int q0 = blockIdx.x * AQT;
    const float* qb = qkv + (size_t)b*N_*768 + h*32;

    // load Q tile (AQT x 32) via float4
    for (int i = tid; i < AQT*8; i += 256) {
        int r = i >> 3, d4 = (i & 7) << 2;
        float4 v = *(const float4*)(qb + (size_t)(q0+r)*768 + d4);
        q_s[r*33+d4+0] = v.x; q_s[r*33+d4+1] = v.y;
        q_s[r*33+d4+2] = v.z; q_s[r*33+d4+3] = v.w;
    }
    __syncthreads();

    int ty = tid >> 5, tx = tid & 31;
    const float scale = 0.17677669529663687f;   // 32^-0.5

    // ---- Phase 1: scores ----
    for (int kt = 0; kt < N_; kt += AKT) {
        for (int i = tid; i < AKT*8; i += 256) {
            int c = i >> 3, d4 = (i & 7) << 2;
            float4 v = *(const float4*)(qb + (size_t)(kt+c)*768 + 256 + d4);
            kv_s[c*33+d4+0] = v.x; kv_s[c*33+d4+1] = v.y;
            kv_s[c*33+d4+2] = v.z; kv_s[c*33+d4+3] = v.w;
        }
        __syncthreads();
        float acc[4][4];
        #pragma unroll
        for (int i = 0; i < 4; i++)
            #pragma unroll
            for (int j = 0; j < 4; j++) acc[i][j] = 0.f;
        #pragma unroll
        for (int d = 0; d < 32; d++) {
            float a[4], bb[4];
            #pragma unroll
            for (int i = 0; i < 4; i++) a[i]  = q_s[(ty*4+i)*33 + d];
            #pragma unroll
            for (int j = 0; j < 4; j++) bb[j] = kv_s[(tx + 32*j)*33 + d];
            #pragma unroll
            for (int i = 0; i < 4; i++)
                #pragma unroll
                for (int j = 0; j < 4; j++)
                    acc[i][j] = fmaf(a[i], bb[j], acc[i][j]);
        }
        #pragma unroll
        for (int i = 0; i < 4; i++)
            #pragma unroll
            for (int j = 0; j < 4; j++)
                s_s[(ty*4+i)*1025 + kt + tx + 32*j] = acc[i][j]*scale;
        __syncthreads();
    }

    // ---- Phase 2: softmax, warp ty handles rows ty*4..ty*4+3 ----
    {
        int r0 = ty*4;
        for (int ri = 0; ri < 4; ri++) {
            int r = r0 + ri;
            float mx = -1e30f;
            for (int c = tx; c < N_; c += 32) mx = fmaxf(mx, s_s[r*1025+c]);
            #pragma unroll
            for (int o = 16; o; o >>= 1) mx = fmaxf(mx, __shfl_xor_sync(0xffffffffu, mx, o));
            float sum = 0.f;
            for (int c = tx; c < N_; c += 32) {
                float e = __expf(s_s[r*1025+c] - mx);
                s_s[r*1025+c] = e;
                sum += e;
            }
            #pragma unroll
            for (int o = 16; o; o >>= 1) sum += __shfl_xor_sync(0xffffffffu, sum, o);
            float inv = 1.f/sum;
            for (int c = tx; c < N_; c += 32) s_s[r*1025+c] *= inv;
        }
    }
    __syncthreads();

    // ---- Phase 3: O = P @ V, 4x4 micro with 4-way key split ----
    int tile = tid & 63, kp = tid >> 6;
    int rr0 = (tile >> 3) << 2, dd0 = (tile & 7) << 2;
    float oacc[4][4];
    #pragma unroll
    for (int i = 0; i < 4; i++)
        #pragma unroll
        for (int j = 0; j < 4; j++) oacc[i][j] = 0.f;

    for (int kt = 0; kt < N_; kt += AKT) {
        for (int i = tid; i < AKT*8; i += 256) {
            int c = i >> 3, d4 = (i & 7) << 2;
            float4 v = *(const float4*)(qb + (size_t)(kt+c)*768 + 512 + d4);
            kv_s[c*33+d4+0] = v.x; kv_s[c*33+d4+1] = v.y;
            kv_s[c*33+d4+2] = v.z; kv_s[c*33+d4+3] = v.w;
        }
        __syncthreads();
        for (int c = kp; c < AKT; c += 4) {
            float p[4], vv[4];
            #pragma unroll
            for (int i = 0; i < 4; i++) p[i]  = s_s[(rr0+i)*1025 + kt + c];
            #pragma unroll
            for (int j = 0; j < 4; j++) vv[j] = kv_s[c*33 + dd0 + j];
            #pragma unroll
            for (int i = 0; i < 4; i++)
                #pragma unroll
                for (int j = 0; j < 4; j++)
                    oacc[i][j] = fmaf(p[i], vv[j], oacc[i][j]);
        }
        __syncthreads();
    }

    // reduce the 4 key-split partials via smem (s_s is free now)
    #pragma unroll
    for (int i = 0; i < 4; i++)
        #pragma unroll
        for (int j = 0; j < 4; j++)
            s_s[kp*1024 + tile*16 + i*4 + j] = oacc[i][j];
    __syncthreads();

    float* ob = out + ((size_t)b*N_ + q0)*C_ + h*32;
    #pragma unroll
    for (int t2 = 0; t2 < 4; t2++) {
        int oi = tid + t2*256;                // 0..1023
        int r = oi >> 5, d = oi & 31;
        int tl = ((r >> 2) << 3) + (d >> 2);
        int off = tl*16 + (r & 3)*4 + (d & 3);
        float v = s_s[off] + s_s[1024+off] + s_s[2048+off] + s_s[3072+off];
        ob[(size_t)r*C_ + d] = v;
    }
}

// ---------------------------------------------------------------------------
// Deformable gather: one warp per (b, n, head); lane = channel d.
// gx = ref.x*32 + off.x - 0.5 (identical rounding to (ref+off/32)*32-0.5).
// ---------------------------------------------------------------------------
__global__ __launch_bounds__(128) void deform_kernel(
    const float* __restrict__ ref, const float* __restrict__ off,
    const float* __restrict__ awl, const float* __restrict__ vp,
    float* __restrict__ out)
{
    int u = (blockIdx.x << 2) + (threadIdx.x >> 5);   // (b*N+n)*8 + h
    int lane = threadIdx.x & 31;
    int h  = u & 7;
    int bn = u >> 3;
    int b  = bn >> 10;

    float rx = ref[(size_t)bn*2 + 0]*32.f - 0.5f;
    float ry = ref[(size_t)bn*2 + 1]*32.f - 0.5f;
    const float* offp = off + (size_t)bn*64 + h*8;
    const float* awp  = awl + (size_t)bn*32 + h*4;

    float a0 = awp[0], a1 = awp[1], a2 = awp[2], a3 = awp[3];
    float mx = fmaxf(fmaxf(a0,a1), fmaxf(a2,a3));
    float e0 = __expf(a0-mx), e1 = __expf(a1-mx), e2 = __expf(a2-mx), e3 = __expf(a3-mx);
    float inv = 1.f/(e0+e1+e2+e3);
    float aw4[4] = {e0*inv, e1*inv, e2*inv, e3*inv};

    const float* vb = vp + (size_t)b*N_*C_ + h*32 + lane;
    float acc = 0.f;
    #pragma unroll
    for (int p = 0; p < 4; p++) {
        float gx = rx + offp[p*2+0];
        float gy = ry + offp[p*2+1];
        float x0f = floorf(gx), y0f = floorf(gy);
        float lx = gx - x0f, ly = gy - y0f;
        int x0 = (int)x0f, y0 = (int)y0f;
        float s = 0.f;
        #pragma unroll
        for (int cy = 0; cy < 2; cy++) {
            int yi = y0 + cy;
            float wy = cy ? ly : (1.f - ly);
            bool vy = (yi >= 0) && (yi < 32);
            int yc = min(max(yi, 0), 31);
            #pragma unroll
            for (int cx = 0; cx < 2; cx++) {
                int xi = x0 + cx;
                float wx = cx ? lx : (1.f - lx);
                bool vx = (xi >= 0) && (xi < 32);
                int xc = min(max(xi, 0), 31);
                float val = (vx && vy) ? vb[(size_t)(yc*32 + xc)*C_] : 0.f;
                s = fmaf(val, wx*wy, s);
            }
        }
        acc = fmaf(aw4[p], s, acc);
    }
    out[(size_t)bn*C_ + h*32 + lane] = acc;
}

// ---------------------------------------------------------------------------
// Launch
// ---------------------------------------------------------------------------
extern "C" void kernel_launch(void* const* d_in, const int* in_sizes, int n_in,
                              void* d_out, int out_size)
{
    const float* x       = (const float*)d_in[0];
    const float* ref     = (const float*)d_in[1];
    const float* value   = (const float*)d_in[2];
    const float* ln1w    = (const float*)d_in[3];
    const float* ln1b    = (const float*)d_in[4];
    const float* ln2w    = (const float*)d_in[5];
    const float* ln2b    = (const float*)d_in[6];
    const float* ln3w    = (const float*)d_in[7];
    const float* ln3b    = (const float*)d_in[8];
    const float* qkv_w   = (const float*)d_in[9];
    const float* proj_w  = (const float*)d_in[10];
    const float* proj_b  = (const float*)d_in[11];
    const float* off_w   = (const float*)d_in[12];
    const float* off_b   = (const float*)d_in[13];
    const float* aw_w    = (const float*)d_in[14];
    const float* aw_b    = (const float*)d_in[15];
    const float* vproj_w = (const float*)d_in[16];
    const float* vproj_b = (const float*)d_in[17];
    const float* oproj_w = (const float*)d_in[18];
    const float* oproj_b = (const float*)d_in[19];
    const float* fc1_w   = (const float*)d_in[20];
    const float* fc1_b   = (const float*)d_in[21];
    const float* fc2_w   = (const float*)d_in[22];
    const float* fc2_b   = (const float*)d_in[23];
    float* out = (float*)d_out;

    float *y, *qkvb, *tmp, *x2, *offb, *awb, *vpb, *h1;
    cudaGetSymbolAddress((void**)&y,    g_y);
    cudaGetSymbolAddress((void**)&qkvb, g_qkv);
    cudaGetSymbolAddress((void**)&tmp,  g_tmp);
    cudaGetSymbolAddress((void**)&x2,   g_x2);
    cudaGetSymbolAddress((void**)&offb, g_off);
    cudaGetSymbolAddress((void**)&awb,  g_awl);
    cudaGetSymbolAddress((void**)&vpb,  g_vp);
    cudaGetSymbolAddress((void**)&h1,   g_h1);

    cudaFuncSetAttribute(attn_kernel,
        cudaFuncAttributeMaxDynamicSharedMemorySize, ASMEM);

    // x1 = x + attn(ln1(x))
    ln_kernel<<<M_, 256>>>(x, ln1w, ln1b, y);
    gemm_kernel<<<dim3(6,128), 256>>>(y, qkv_w, nullptr, nullptr, qkvb, M_, 768, 256, 0);
    attn_kernel<<<dim3(32, 8, 16), 256, ASMEM>>>(qkvb, tmp);
    gemm_kernel<<<dim3(2,128), 256>>>(tmp, proj_w, proj_b, x, x2, M_, 256, 256, 0);

    // x2 = x1 + deform(ln2(x1))
    ln_kernel<<<M_, 256>>>(x2, ln2w, ln2b, y);
    gemm_kernel<<<dim3(1,128), 256>>>(y, off_w, off_b, nullptr, offb, M_, 64, 256, 0);
    gemm_kernel<<<dim3(1,128), 256>>>(y, aw_w,  aw_b,  nullptr, awb,  M_, 32, 256, 0);
    gemm_kernel<<<dim3(2,128), 256>>>(value, vproj_w, vproj_b, nullptr, vpb, M_, 256, 256, 0);
    deform_kernel<<<32768, 128>>>(ref, offb, awb, vpb, tmp);
    gemm_kernel<<<dim3(2,128), 256>>>(tmp, oproj_w, oproj_b, x2, x2, M_, 256, 256, 0);

    // out = x2 + fc2(gelu(fc1(ln3(x2))))
    ln_kernel<<<M_, 256>>>(x2, ln3w, ln3b, y);
    gemm_kernel<<<dim3(8,128), 256>>>(y, fc1_w, fc1_b, nullptr, h1, M_, 1024, 256, 1);
    gemm_kernel<<<dim3(2,128), 256>>>(h1, fc2_w, fc2_b, x2, out, M_, 256, 1024, 0);
}

// round 5
// speedup vs baseline: 2.2984x; 2.2984x over previous
#include <cuda_runtime.h>
#include <cstdint>
#include <math.h>

typedef unsigned int u32;

// Problem constants
#define B_  16
#define N_  1024
#define C_  256
#define NH_ 8
#define DH_ 32
#define M_  (B_*N_)      // 16384 rows
#define HID_ 1024

// ---------------------------------------------------------------------------
// Scratch (static __device__ arrays; no allocations allowed)
// ---------------------------------------------------------------------------
__device__ float g_y  [M_*C_];
__device__ float g_qkv[M_*3*C_];
__device__ float g_tmp[M_*C_];
__device__ float g_x2 [M_*C_];
__device__ float g_off[M_*64];
__device__ float g_awl[M_*32];
__device__ float g_vp [M_*C_];
__device__ float g_h1 [M_*HID_];

// ---------------------------------------------------------------------------
// tf32 helpers
// ---------------------------------------------------------------------------
__device__ __forceinline__ float tf32r(float x) {
    u32 u;
    asm("cvt.rna.tf32.f32 %0, %1;" : "=r"(u) : "f"(x));
    return __uint_as_float(u);
}

__device__ __forceinline__ void mma_tf32(float (&d)[4],
                                         const u32 (&a)[4],
                                         const u32 (&b)[2]) {
    asm volatile(
        "mma.sync.aligned.m16n8k8.row.col.f32.tf32.tf32.f32 "
        "{%0,%1,%2,%3}, {%4,%5,%6,%7}, {%8,%9}, {%0,%1,%2,%3};"
        : "+f"(d[0]), "+f"(d[1]), "+f"(d[2]), "+f"(d[3])
        : "r"(a[0]), "r"(a[1]), "r"(a[2]), "r"(a[3]),
          "r"(b[0]), "r"(b[1]));
}

// ---------------------------------------------------------------------------
// LayerNorm: one block per row, 256 threads (C=256)
// ---------------------------------------------------------------------------
__global__ __launch_bounds__(256) void ln_kernel(
    const float* __restrict__ in, const float* __restrict__ w,
    const float* __restrict__ b, float* __restrict__ out)
{
    __shared__ float red[8];
    int row = blockIdx.x;
    int t = threadIdx.x;
    float v = in[(size_t)row*C_ + t];
    float s = v;
    #pragma unroll
    for (int o = 16; o; o >>= 1) s += __shfl_xor_sync(0xffffffffu, s, o);
    if ((t & 31) == 0) red[t >> 5] = s;
    __syncthreads();
    float tot = 0.f;
    #pragma unroll
    for (int i = 0; i < 8; i++) tot += red[i];
    float mean = tot * (1.0f/256.0f);
    __syncthreads();
    float d = v - mean;
    s = d*d;
    #pragma unroll
    for (int o = 16; o; o >>= 1) s += __shfl_xor_sync(0xffffffffu, s, o);
    if ((t & 31) == 0) red[t >> 5] = s;
    __syncthreads();
    tot = 0.f;
    #pragma unroll
    for (int i = 0; i < 8; i++) tot += red[i];
    float rs = rsqrtf(tot*(1.0f/256.0f) + 1e-5f);
    out[(size_t)row*C_ + t] = d*rs*w[t] + b[t];
}

// ---------------------------------------------------------------------------
// Legacy fp32 GEMM (exact) — used only for the small off/aw projections that
// feed floorf in the deform gather.
// ---------------------------------------------------------------------------
#define GBM 128
#define GBN 128
#define GBK 16

__global__ __launch_bounds__(256) void gemm_kernel(
    const float* __restrict__ X, const float* __restrict__ W,
    const float* __restrict__ bias, const float* __restrict__ res,
    float* __restrict__ Y, int M, int Nout, int K, int act)
{
    __shared__ float sX[GBK][GBM+1];
    __shared__ float sW[GBK][GBN+1];
    int tid = threadIdx.x;
    int tx = tid & 15, ty = tid >> 4;
    int m0 = blockIdx.y * GBM;
    int n0 = blockIdx.x * GBN;

    float acc[8][8];
    #pragma unroll
    for (int i = 0; i < 8; i++)
        #pragma unroll
        for (int j = 0; j < 8; j++) acc[i][j] = 0.f;

    for (int k0 = 0; k0 < K; k0 += GBK) {
        #pragma unroll
        for (int v = 0; v < 2; v++) {
            int idx = tid + (v << 8);
            int mm  = idx >> 2;
            int kq  = (idx & 3) << 2;
            float4 xv = *(const float4*)(X + (size_t)(m0+mm)*K + k0 + kq);
            sX[kq+0][mm] = xv.x; sX[kq+1][mm] = xv.y;
            sX[kq+2][mm] = xv.z; sX[kq+3][mm] = xv.w;
            float4 wv = make_float4(0.f, 0.f, 0.f, 0.f);
            if (n0 + mm < Nout)
                wv = *(const float4*)(W + (size_t)(n0+mm)*K + k0 + kq);
            sW[kq+0][mm] = wv.x; sW[kq+1][mm] = wv.y;
            sW[kq+2][mm] = wv.z; sW[kq+3][mm] = wv.w;
        }
        __syncthreads();
        #pragma unroll
        for (int k = 0; k < GBK; k++) {
            float a[8], bb[8];
            #pragma unroll
            for (int i = 0; i < 8; i++) a[i]  = sX[k][ty + 16*i];
            #pragma unroll
            for (int j = 0; j < 8; j++) bb[j] = sW[k][tx + 16*j];
            #pragma unroll
            for (int i = 0; i < 8; i++)
                #pragma unroll
                for (int j = 0; j < 8; j++)
                    acc[i][j] = fmaf(a[i], bb[j], acc[i][j]);
        }
        __syncthreads();
    }

    #pragma unroll
    for (int i = 0; i < 8; i++) {
        int m = m0 + ty + 16*i;
        #pragma unroll
        for (int j = 0; j < 8; j++) {
            int n = n0 + tx + 16*j;
            if (n < Nout) {
                float v = acc[i][j];
                if (bias) v += bias[n];
                if (act)  v *= normcdff(v);
                if (res)  v += res[(size_t)m*Nout + n];
                Y[(size_t)m*Nout + n] = v;
            }
        }
    }
}

// ---------------------------------------------------------------------------
// tf32 tensor-core GEMM: Y[M,Nout] = X[M,K] @ W[Nout,K]^T (+bias)(+gelu)(+res)
// Block 128x128, BK=32, 8 warps in 2x4; warp tile 64x32 = 4 m16 x 4 n8 tiles.
// Requires M%128==0, Nout%128==0, K%32==0 (true for all tc call sites).
// smem stride 36 (== 4 mod 32) makes every fragment LDS conflict-free.
// ---------------------------------------------------------------------------
#define TSTR 36

__global__ __launch_bounds__(256) void gemm_tc(
    const float* __restrict__ X, const float* __restrict__ W,
    const float* __restrict__ bias, const float* __restrict__ res,
    float* __restrict__ Y, int M, int Nout, int K, int act)
{
    __shared__ float sX[128*TSTR];
    __shared__ float sW[128*TSTR];
    int tid  = threadIdx.x;
    int warp = tid >> 5, lane = tid & 31;
    int g = lane >> 2, t = lane & 3;
    int wm0 = (warp >> 2) * 64;
    int wn0 = (warp & 3) * 32;
    int m0 = blockIdx.y * 128, n0 = blockIdx.x * 128;

    float acc[4][4][4];
    #pragma unroll
    for (int mt = 0; mt < 4; mt++)
        #pragma unroll
        for (int nt = 0; nt < 4; nt++)
            #pragma unroll
            for (int c = 0; c < 4; c++) acc[mt][nt][c] = 0.f;

    for (int k0 = 0; k0 < K; k0 += 32) {
        #pragma unroll
        for (int i = 0; i < 4; i++) {
            int idx = tid + (i << 8);
            int r  = idx >> 3;
            int c4 = (idx & 7) << 2;
            float4 xv = *(const float4*)(X + (size_t)(m0+r)*K + k0 + c4);
            sX[r*TSTR + c4 + 0] = tf32r(xv.x);
            sX[r*TSTR + c4 + 1] = tf32r(xv.y);
            sX[r*TSTR + c4 + 2] = tf32r(xv.z);
            sX[r*TSTR + c4 + 3] = tf32r(xv.w);
            float4 wv = *(const float4*)(W + (size_t)(n0+r)*K + k0 + c4);
            sW[r*TSTR + c4 + 0] = tf32r(wv.x);
            sW[r*TSTR + c4 + 1] = tf32r(wv.y);
            sW[r*TSTR + c4 + 2] = tf32r(wv.z);
            sW[r*TSTR + c4 + 3] = tf32r(wv.w);
        }
        __syncthreads();
        #pragma unroll
        for (int ks = 0; ks < 4; ks++) {
            int kc = ks*8 + t;
            u32 a[4][4];
            #pragma unroll
            for (int mt = 0; mt < 4; mt++) {
                int r = wm0 + mt*16 + g;
                a[mt][0] = __float_as_uint(sX[r*TSTR     + kc]);
                a[mt][1] = __float_as_uint(sX[(r+8)*TSTR + kc]);
                a[mt][2] = __float_as_uint(sX[r*TSTR     + kc + 4]);
                a[mt][3] = __float_as_uint(sX[(r+8)*TSTR + kc + 4]);
            }
            u32 bb[4][2];
            #pragma unroll
            for (int nt = 0; nt < 4; nt++) {
                int r = wn0 + nt*8 + g;
                bb[nt][0] = __float_as_uint(sW[r*TSTR + kc]);
                bb[nt][1] = __float_as_uint(sW[r*TSTR + kc + 4]);
            }
            #pragma unroll
            for (int mt = 0; mt < 4; mt++)
                #pragma unroll
                for (int nt = 0; nt < 4; nt++)
                    mma_tf32(acc[mt][nt], a[mt], bb[nt]);
        }
        __syncthreads();
    }

    #pragma unroll
    for (int mt = 0; mt < 4; mt++) {
        #pragma unroll
        for (int nt = 0; nt < 4; nt++) {
            int n = n0 + wn0 + nt*8 + 2*t;
            #pragma unroll
            for (int half = 0; half < 2; half++) {
                int m = m0 + wm0 + mt*16 + g + half*8;
                float v0 = acc[mt][nt][half*2 + 0];
                float v1 = acc[mt][nt][half*2 + 1];
                if (bias) { v0 += bias[n]; v1 += bias[n+1]; }
                if (act)  { v0 *= normcdff(v0); v1 *= normcdff(v1); }
                if (res)  { v0 += res[(size_t)m*Nout + n];
                            v1 += res[(size_t)m*Nout + n + 1]; }
                *(float2*)(Y + (size_t)m*Nout + n) = make_float2(v0, v1);
            }
        }
    }
}

// ---------------------------------------------------------------------------
// Attention (tf32 tensor cores): per (b, h, 32-query tile), 256 threads.
// Phase1: S = QK^T via mma (warp owns 16 keys of each 128-chunk).
// Phase2: row softmax (fp32, tf32-rounded on writeback).
// Phase3: O = P@V via mma with 8-way key split + smem reduction.
// qkv layout: (b*N+n)*768 + s*256 + h*32 + d, s in {q,k,v}
// ---------------------------------------------------------------------------
#define AQT 32
#define AKT 128
#define SSTR 1028
#define ASMEM ((AQT*TSTR + AKT*TSTR + AQT*SSTR)*4)

__global__ __launch_bounds__(256) void attn_tc(
    const float* __restrict__ qkv, float* __restrict__ out)
{
    extern __shared__ float sm[];
    float* q_s  = sm;                    // AQT * 36
    float* kv_s = sm + AQT*TSTR;         // AKT * 36
    float* s_s  = kv_s + AKT*TSTR;       // AQT * 1028

    int tid  = threadIdx.x;
    int warp = tid >> 5, lane = tid & 31;
    int g = lane >> 2, t = lane & 3;
    int b = blockIdx.z, h = blockIdx.y;
    int q0 = blockIdx.x * AQT;
    const float* qb = qkv + (size_t)b*N_*768 + h*32;
    const float scale = 0.17677669529663687f;   // 32^-0.5

    // load Q tile (32 x 32), tf32-rounded
    {
        int r  = tid >> 3;
        int c4 = (tid & 7) << 2;
        float4 v = *(const float4*)(qb + (size_t)(q0+r)*768 + c4);
        q_s[r*TSTR + c4 + 0] = tf32r(v.x);
        q_s[r*TSTR + c4 + 1] = tf32r(v.y);
        q_s[r*TSTR + c4 + 2] = tf32r(v.z);
        q_s[r*TSTR + c4 + 3] = tf32r(v.w);
    }
    __syncthreads();

    // ---- Phase 1: scores ----
    for (int kt = 0; kt < N_; kt += AKT) {
        #pragma unroll
        for (int i = 0; i < 4; i++) {
            int idx = tid + (i << 8);
            int r  = idx >> 3;
            int c4 = (idx & 7) << 2;
            float4 v = *(const float4*)(qb + (size_t)(kt+r)*768 + 256 + c4);
            kv_s[r*TSTR + c4 + 0] = tf32r(v.x);
            kv_s[r*TSTR + c4 + 1] = tf32r(v.y);
            kv_s[r*TSTR + c4 + 2] = tf32r(v.z);
            kv_s[r*TSTR + c4 + 3] = tf32r(v.w);
        }
        __syncthreads();

        float sacc[2][2][4];
        #pragma unroll
        for (int mt = 0; mt < 2; mt++)
            #pragma unroll
            for (int nt = 0; nt < 2; nt++)
                #pragma unroll
                for (int c = 0; c < 4; c++) sacc[mt][nt][c] = 0.f;

        int n0w = warp * 16;
        #pragma unroll
        for (int ks = 0; ks < 4; ks++) {
            int kc = ks*8 + t;
            u32 a[2][4];
            #pragma unroll
            for (int mt = 0; mt < 2; mt++) {
                int r = mt*16 + g;
                a[mt][0] = __float_as_uint(q_s[r*TSTR     + kc]);
                a[mt][1] = __float_as_uint(q_s[(r+8)*TSTR + kc]);
                a[mt][2] = __float_as_uint(q_s[r*TSTR     + kc + 4]);
                a[mt][3] = __float_as_uint(q_s[(r+8)*TSTR + kc + 4]);
            }
            u32 bb[2][2];
            #pragma unroll
            for (int nt = 0; nt < 2; nt++) {
                int r = n0w + nt*8 + g;
                bb[nt][0] = __float_as_uint(kv_s[r*TSTR + kc]);
                bb[nt][1] = __float_as_uint(kv_s[r*TSTR + kc + 4]);
            }
            #pragma unroll
            for (int mt = 0; mt < 2; mt++)
                #pragma unroll
                for (int nt = 0; nt < 2; nt++)
                    mma_tf32(sacc[mt][nt], a[mt], bb[nt]);
        }
        #pragma unroll
        for (int mt = 0; mt < 2; mt++)
            #pragma unroll
            for (int nt = 0; nt < 2; nt++) {
                int col = kt + n0w + nt*8 + 2*t;
                int r0 = mt*16 + g;
                s_s[r0*SSTR     + col    ] = sacc[mt][nt][0]*scale;
                s_s[r0*SSTR     + col + 1] = sacc[mt][nt][1]*scale;
                s_s[(r0+8)*SSTR + col    ] = sacc[mt][nt][2]*scale;
                s_s[(r0+8)*SSTR + col + 1] = sacc[mt][nt][3]*scale;
            }
        __syncthreads();
    }

    // ---- Phase 2: softmax; warp w handles rows w*4..w*4+3 ----
    {
        int r0 = warp*4;
        for (int ri = 0; ri < 4; ri++) {
            int r = r0 + ri;
            float mx = -1e30f;
            for (int c = lane; c < N_; c += 32) mx = fmaxf(mx, s_s[r*SSTR+c]);
            #pragma unroll
            for (int o = 16; o; o >>= 1)
                mx = fmaxf(mx, __shfl_xor_sync(0xffffffffu, mx, o));
            float sum = 0.f;
            for (int c = lane; c < N_; c += 32) {
                float e = __expf(s_s[r*SSTR+c] - mx);
                s_s[r*SSTR+c] = e;
                sum += e;
            }
            #pragma unroll
            for (int o = 16; o; o >>= 1)
                sum += __shfl_xor_sync(0xffffffffu, sum, o);
            float inv = 1.f/sum;
            for (int c = lane; c < N_; c += 32)
                s_s[r*SSTR+c] = tf32r(s_s[r*SSTR+c] * inv);
        }
    }
    __syncthreads();

    // ---- Phase 3: O = P@V, 8-way key split across warps ----
    float oacc[2][4][4];
    #pragma unroll
    for (int mt = 0; mt < 2; mt++)
        #pragma unroll
        for (int nt = 0; nt < 4; nt++)
            #pragma unroll
            for (int c = 0; c < 4; c++) oacc[mt][nt][c] = 0.f;

    for (int kt = 0; kt < N_; kt += AKT) {
        #pragma unroll
        for (int i = 0; i < 4; i++) {
            int idx = tid + (i << 8);
            int r  = idx >> 3;
            int c4 = (idx & 7) << 2;
            float4 v = *(const float4*)(qb + (size_t)(kt+r)*768 + 512 + c4);
            kv_s[r*TSTR + c4 + 0] = tf32r(v.x);
            kv_s[r*TSTR + c4 + 1] = tf32r(v.y);
            kv_s[r*TSTR + c4 + 2] = tf32r(v.z);
            kv_s[r*TSTR + c4 + 3] = tf32r(v.w);
        }
        __syncthreads();

        #pragma unroll
        for (int ks2 = 0; ks2 < 2; ks2++) {
            int tokl = warp*16 + ks2*8;          // token offset in chunk
            int tok  = kt + tokl;                // token offset in s_s
            u32 a[2][4];
            #pragma unroll
            for (int mt = 0; mt < 2; mt++) {
                int r = mt*16 + g;
                a[mt][0] = __float_as_uint(s_s[r*SSTR     + tok + t]);
                a[mt][1] = __float_as_uint(s_s[(r+8)*SSTR + tok + t]);
                a[mt][2] = __float_as_uint(s_s[r*SSTR     + tok + t + 4]);
                a[mt][3] = __float_as_uint(s_s[(r+8)*SSTR + tok + t + 4]);
            }
            u32 bb[4][2];
            #pragma unroll
            for (int nt = 0; nt < 4; nt++) {
                int d = nt*8 + g;
                bb[nt][0] = __float_as_uint(kv_s[(tokl + t)*TSTR     + d]);
                bb[nt][1] = __float_as_uint(kv_s[(tokl + t + 4)*TSTR + d]);
            }
            #pragma unroll
            for (int mt = 0; mt < 2; mt++)
                #pragma unroll
                for (int nt = 0; nt < 4; nt++)
                    mma_tf32(oacc[mt][nt], a[mt], bb[nt]);
        }
        __syncthreads();
    }

    // cross-warp reduction of the 8 key-split partials (s_s is free now)
    #pragma unroll
    for (int mt = 0; mt < 2; mt++)
        #pragma unroll
        for (int nt = 0; nt < 4; nt++) {
            int d  = nt*8 + 2*t;
            int r0 = mt*16 + g;
            float* base = s_s + warp*1024;
            base[r0*32     + d    ] = oacc[mt][nt][0];
            base[r0*32     + d + 1] = oacc[mt][nt][1];
            base[(r0+8)*32 + d    ] = oacc[mt][nt][2];
            base[(r0+8)*32 + d + 1] = oacc[mt][nt][3];
        }
    __syncthreads();

    float* ob = out + ((size_t)b*N_ + q0)*C_ + h*32;
    #pragma unroll
    for (int t2 = 0; t2 < 4; t2++) {
        int oi = tid + t2*256;            // 0..1023
        int r = oi >> 5, d = oi & 31;
        float v = 0.f;
        #pragma unroll
        for (int w = 0; w < 8; w++) v += s_s[w*1024 + r*32 + d];
        ob[(size_t)r*C_ + d] = v;
    }
}

// ---------------------------------------------------------------------------
// Deformable gather: one warp per (b, n, head); lane = channel d.
// ---------------------------------------------------------------------------
__global__ __launch_bounds__(128) void deform_kernel(
    const float* __restrict__ ref, const float* __restrict__ off,
    const float* __restrict__ awl, const float* __restrict__ vp,
    float* __restrict__ out)
{
    int u = (blockIdx.x << 2) + (threadIdx.x >> 5);
    int lane = threadIdx.x & 31;
    int h  = u & 7;
    int bn = u >> 3;
    int b  = bn >> 10;

    float rx = ref[(size_t)bn*2 + 0]*32.f - 0.5f;
    float ry = ref[(size_t)bn*2 + 1]*32.f - 0.5f;
    const float* offp = off + (size_t)bn*64 + h*8;
    const float* awp  = awl + (size_t)bn*32 + h*4;

    float a0 = awp[0], a1 = awp[1], a2 = awp[2], a3 = awp[3];
    float mx = fmaxf(fmaxf(a0,a1), fmaxf(a2,a3));
    float e0 = __expf(a0-mx), e1 = __expf(a1-mx), e2 = __expf(a2-mx), e3 = __expf(a3-mx);
    float inv = 1.f/(e0+e1+e2+e3);
    float aw4[4] = {e0*inv, e1*inv, e2*inv, e3*inv};

    const float* vb = vp + (size_t)b*N_*C_ + h*32 + lane;
    float acc = 0.f;
    #pragma unroll
    for (int p = 0; p < 4; p++) {
        float gx = rx + offp[p*2+0];
        float gy = ry + offp[p*2+1];
        float x0f = floorf(gx), y0f = floorf(gy);
        float lx = gx - x0f, ly = gy - y0f;
        int x0 = (int)x0f, y0 = (int)y0f;
        float s = 0.f;
        #pragma unroll
        for (int cy = 0; cy < 2; cy++) {
            int yi = y0 + cy;
            float wy = cy ? ly : (1.f - ly);
            bool vy = (yi >= 0) && (yi < 32);
            int yc = min(max(yi, 0), 31);
            #pragma unroll
            for (int cx = 0; cx < 2; cx++) {
                int xi = x0 + cx;
                float wx = cx ? lx : (1.f - lx);
                bool vx = (xi >= 0) && (xi < 32);
                int xc = min(max(xi, 0), 31);
                float val = (vx && vy) ? vb[(size_t)(yc*32 + xc)*C_] : 0.f;
                s = fmaf(val, wx*wy, s);
            }
        }
        acc = fmaf(aw4[p], s, acc);
    }
    out[(size_t)bn*C_ + h*32 + lane] = acc;
}

// ---------------------------------------------------------------------------
// Launch
// ---------------------------------------------------------------------------
extern "C" void kernel_launch(void* const* d_in, const int* in_sizes, int n_in,
                              void* d_out, int out_size)
{
    const float* x       = (const float*)d_in[0];
    const float* ref     = (const float*)d_in[1];
    const float* value   = (const float*)d_in[2];
    const float* ln1w    = (const float*)d_in[3];
    const float* ln1b    = (const float*)d_in[4];
    const float* ln2w    = (const float*)d_in[5];
    const float* ln2b    = (const float*)d_in[6];
    const float* ln3w    = (const float*)d_in[7];
    const float* ln3b    = (const float*)d_in[8];
    const float* qkv_w   = (const float*)d_in[9];
    const float* proj_w  = (const float*)d_in[10];
    const float* proj_b  = (const float*)d_in[11];
    const float* off_w   = (const float*)d_in[12];
    const float* off_b   = (const float*)d_in[13];
    const float* aw_w    = (const float*)d_in[14];
    const float* aw_b    = (const float*)d_in[15];
    const float* vproj_w = (const float*)d_in[16];
    const float* vproj_b = (const float*)d_in[17];
    const float* oproj_w = (const float*)d_in[18];
    const float* oproj_b = (const float*)d_in[19];
    const float* fc1_w   = (const float*)d_in[20];
    const float* fc1_b   = (const float*)d_in[21];
    const float* fc2_w   = (const float*)d_in[22];
    const float* fc2_b   = (const float*)d_in[23];
    float* out = (float*)d_out;

    float *y, *qkvb, *tmp, *x2, *offb, *awb, *vpb, *h1;
    cudaGetSymbolAddress((void**)&y,    g_y);
    cudaGetSymbolAddress((void**)&qkvb, g_qkv);
    cudaGetSymbolAddress((void**)&tmp,  g_tmp);
    cudaGetSymbolAddress((void**)&x2,   g_x2);
    cudaGetSymbolAddress((void**)&offb, g_off);
    cudaGetSymbolAddress((void**)&awb,  g_awl);
    cudaGetSymbolAddress((void**)&vpb,  g_vp);
    cudaGetSymbolAddress((void**)&h1,   g_h1);

    cudaFuncSetAttribute(attn_tc,
        cudaFuncAttributeMaxDynamicSharedMemorySize, ASMEM);

    // x1 = x + attn(ln1(x))
    ln_kernel<<<M_, 256>>>(x, ln1w, ln1b, y);
    gemm_tc<<<dim3(6,128), 256>>>(y, qkv_w, nullptr, nullptr, qkvb, M_, 768, 256, 0);
    attn_tc<<<dim3(32, 8, 16), 256, ASMEM>>>(qkvb, tmp);
    gemm_tc<<<dim3(2,128), 256>>>(tmp, proj_w, proj_b, x, x2, M_, 256, 256, 0);

    // x2 = x1 + deform(ln2(x1))
    ln_kernel<<<M_, 256>>>(x2, ln2w, ln2b, y);
    gemm_kernel<<<dim3(1,128), 256>>>(y, off_w, off_b, nullptr, offb, M_, 64, 256, 0);
    gemm_kernel<<<dim3(1,128), 256>>>(y, aw_w,  aw_b,  nullptr, awb,  M_, 32, 256, 0);
    gemm_tc<<<dim3(2,128), 256>>>(value, vproj_w, vproj_b, nullptr, vpb, M_, 256, 256, 0);
    deform_kernel<<<32768, 128>>>(ref, offb, awb, vpb, tmp);
    gemm_tc<<<dim3(2,128), 256>>>(tmp, oproj_w, oproj_b, x2, x2, M_, 256, 256, 0);

    // out = x2 + fc2(gelu(fc1(ln3(x2))))
    ln_kernel<<<M_, 256>>>(x2, ln3w, ln3b, y);
    gemm_tc<<<dim3(8,128), 256>>>(y, fc1_w, fc1_b, nullptr, h1, M_, 1024, 256, 1);
    gemm_tc<<<dim3(2,128), 256>>>(h1, fc2_w, fc2_b, x2, out, M_, 256, 1024, 0);
}

// round 6
// speedup vs baseline: 3.2701x; 1.4228x over previous
#include <cuda_runtime.h>
#include <cstdint>
#include <math.h>

typedef unsigned int u32;

// Problem constants
#define B_  16
#define N_  1024
#define C_  256
#define NH_ 8
#define DH_ 32
#define M_  (B_*N_)      // 16384 rows
#define HID_ 1024

// ---------------------------------------------------------------------------
// Scratch (static __device__ arrays; no allocations allowed)
// ---------------------------------------------------------------------------
__device__ float g_y  [M_*C_];
__device__ float g_qkv[M_*3*C_];
__device__ float g_tmp[M_*C_];
__device__ float g_x2 [M_*C_];
__device__ float g_off[M_*64];
__device__ float g_awl[M_*32];
__device__ float g_vp [M_*C_];
__device__ float g_h1 [M_*HID_];

// ---------------------------------------------------------------------------
// tf32 helpers
// ---------------------------------------------------------------------------
__device__ __forceinline__ float tf32r(float x) {
    u32 u;
    asm("cvt.rna.tf32.f32 %0, %1;" : "=r"(u) : "f"(x));
    return __uint_as_float(u);
}

__device__ __forceinline__ void mma_tf32(float (&d)[4],
                                         const u32 (&a)[4],
                                         const u32 (&b)[2]) {
    asm volatile(
        "mma.sync.aligned.m16n8k8.row.col.f32.tf32.tf32.f32 "
        "{%0,%1,%2,%3}, {%4,%5,%6,%7}, {%8,%9}, {%0,%1,%2,%3};"
        : "+f"(d[0]), "+f"(d[1]), "+f"(d[2]), "+f"(d[3])
        : "r"(a[0]), "r"(a[1]), "r"(a[2]), "r"(a[3]),
          "r"(b[0]), "r"(b[1]));
}

// ---------------------------------------------------------------------------
// LayerNorm: one block per row, 256 threads (C=256)
// ---------------------------------------------------------------------------
__global__ __launch_bounds__(256) void ln_kernel(
    const float* __restrict__ in, const float* __restrict__ w,
    const float* __restrict__ b, float* __restrict__ out)
{
    __shared__ float red[8];
    int row = blockIdx.x;
    int t = threadIdx.x;
    float v = in[(size_t)row*C_ + t];
    float s = v;
    #pragma unroll
    for (int o = 16; o; o >>= 1) s += __shfl_xor_sync(0xffffffffu, s, o);
    if ((t & 31) == 0) red[t >> 5] = s;
    __syncthreads();
    float tot = 0.f;
    #pragma unroll
    for (int i = 0; i < 8; i++) tot += red[i];
    float mean = tot * (1.0f/256.0f);
    __syncthreads();
    float d = v - mean;
    s = d*d;
    #pragma unroll
    for (int o = 16; o; o >>= 1) s += __shfl_xor_sync(0xffffffffu, s, o);
    if ((t & 31) == 0) red[t >> 5] = s;
    __syncthreads();
    tot = 0.f;
    #pragma unroll
    for (int i = 0; i < 8; i++) tot += red[i];
    float rs = rsqrtf(tot*(1.0f/256.0f) + 1e-5f);
    out[(size_t)row*C_ + t] = d*rs*w[t] + b[t];
}

// ---------------------------------------------------------------------------
// Legacy fp32 GEMM (exact) — used only for the small off/aw projections that
// feed floorf in the deform gather.
// ---------------------------------------------------------------------------
#define GBM 128
#define GBN 128
#define GBK 16

__global__ __launch_bounds__(256) void gemm_kernel(
    const float* __restrict__ X, const float* __restrict__ W,
    const float* __restrict__ bias, const float* __restrict__ res,
    float* __restrict__ Y, int M, int Nout, int K, int act)
{
    __shared__ float sX[GBK][GBM+1];
    __shared__ float sW[GBK][GBN+1];
    int tid = threadIdx.x;
    int tx = tid & 15, ty = tid >> 4;
    int m0 = blockIdx.y * GBM;
    int n0 = blockIdx.x * GBN;

    float acc[8][8];
    #pragma unroll
    for (int i = 0; i < 8; i++)
        #pragma unroll
        for (int j = 0; j < 8; j++) acc[i][j] = 0.f;

    for (int k0 = 0; k0 < K; k0 += GBK) {
        #pragma unroll
        for (int v = 0; v < 2; v++) {
            int idx = tid + (v << 8);
            int mm  = idx >> 2;
            int kq  = (idx & 3) << 2;
            float4 xv = *(const float4*)(X + (size_t)(m0+mm)*K + k0 + kq);
            sX[kq+0][mm] = xv.x; sX[kq+1][mm] = xv.y;
            sX[kq+2][mm] = xv.z; sX[kq+3][mm] = xv.w;
            float4 wv = make_float4(0.f, 0.f, 0.f, 0.f);
            if (n0 + mm < Nout)
                wv = *(const float4*)(W + (size_t)(n0+mm)*K + k0 + kq);
            sW[kq+0][mm] = wv.x; sW[kq+1][mm] = wv.y;
            sW[kq+2][mm] = wv.z; sW[kq+3][mm] = wv.w;
        }
        __syncthreads();
        #pragma unroll
        for (int k = 0; k < GBK; k++) {
            float a[8], bb[8];
            #pragma unroll
            for (int i = 0; i < 8; i++) a[i]  = sX[k][ty + 16*i];
            #pragma unroll
            for (int j = 0; j < 8; j++) bb[j] = sW[k][tx + 16*j];
            #pragma unroll
            for (int i = 0; i < 8; i++)
                #pragma unroll
                for (int j = 0; j < 8; j++)
                    acc[i][j] = fmaf(a[i], bb[j], acc[i][j]);
        }
        __syncthreads();
    }

    #pragma unroll
    for (int i = 0; i < 8; i++) {
        int m = m0 + ty + 16*i;
        #pragma unroll
        for (int j = 0; j < 8; j++) {
            int n = n0 + tx + 16*j;
            if (n < Nout) {
                float v = acc[i][j];
                if (bias) v += bias[n];
                if (act)  v *= normcdff(v);
                if (res)  v += res[(size_t)m*Nout + n];
                Y[(size_t)m*Nout + n] = v;
            }
        }
    }
}

// ---------------------------------------------------------------------------
// tf32 tensor-core GEMM: Y[M,Nout] = X[M,K] @ W[Nout,K]^T (+bias)(+gelu)(+res)
// Block 128x128, BK=32, 8 warps in 2x4; warp tile 64x32 = 4 m16 x 4 n8 tiles.
// smem stride 36 (== 4 mod 32) makes every fragment LDS conflict-free.
// ---------------------------------------------------------------------------
#define TSTR 36

__global__ __launch_bounds__(256) void gemm_tc(
    const float* __restrict__ X, const float* __restrict__ W,
    const float* __restrict__ bias, const float* __restrict__ res,
    float* __restrict__ Y, int M, int Nout, int K, int act)
{
    __shared__ float sX[128*TSTR];
    __shared__ float sW[128*TSTR];
    int tid  = threadIdx.x;
    int warp = tid >> 5, lane = tid & 31;
    int g = lane >> 2, t = lane & 3;
    int wm0 = (warp >> 2) * 64;
    int wn0 = (warp & 3) * 32;
    int m0 = blockIdx.y * 128, n0 = blockIdx.x * 128;

    float acc[4][4][4];
    #pragma unroll
    for (int mt = 0; mt < 4; mt++)
        #pragma unroll
        for (int nt = 0; nt < 4; nt++)
            #pragma unroll
            for (int c = 0; c < 4; c++) acc[mt][nt][c] = 0.f;

    for (int k0 = 0; k0 < K; k0 += 32) {
        #pragma unroll
        for (int i = 0; i < 4; i++) {
            int idx = tid + (i << 8);
            int r  = idx >> 3;
            int c4 = (idx & 7) << 2;
            float4 xv = *(const float4*)(X + (size_t)(m0+r)*K + k0 + c4);
            sX[r*TSTR + c4 + 0] = tf32r(xv.x);
            sX[r*TSTR + c4 + 1] = tf32r(xv.y);
            sX[r*TSTR + c4 + 2] = tf32r(xv.z);
            sX[r*TSTR + c4 + 3] = tf32r(xv.w);
            float4 wv = *(const float4*)(W + (size_t)(n0+r)*K + k0 + c4);
            sW[r*TSTR + c4 + 0] = tf32r(wv.x);
            sW[r*TSTR + c4 + 1] = tf32r(wv.y);
            sW[r*TSTR + c4 + 2] = tf32r(wv.z);
            sW[r*TSTR + c4 + 3] = tf32r(wv.w);
        }
        __syncthreads();
        #pragma unroll
        for (int ks = 0; ks < 4; ks++) {
            int kc = ks*8 + t;
            u32 a[4][4];
            #pragma unroll
            for (int mt = 0; mt < 4; mt++) {
                int r = wm0 + mt*16 + g;
                a[mt][0] = __float_as_uint(sX[r*TSTR     + kc]);
                a[mt][1] = __float_as_uint(sX[(r+8)*TSTR + kc]);
                a[mt][2] = __float_as_uint(sX[r*TSTR     + kc + 4]);
                a[mt][3] = __float_as_uint(sX[(r+8)*TSTR + kc + 4]);
            }
            u32 bb[4][2];
            #pragma unroll
            for (int nt = 0; nt < 4; nt++) {
                int r = wn0 + nt*8 + g;
                bb[nt][0] = __float_as_uint(sW[r*TSTR + kc]);
                bb[nt][1] = __float_as_uint(sW[r*TSTR + kc + 4]);
            }
            #pragma unroll
            for (int mt = 0; mt < 4; mt++)
                #pragma unroll
                for (int nt = 0; nt < 4; nt++)
                    mma_tf32(acc[mt][nt], a[mt], bb[nt]);
        }
        __syncthreads();
    }

    #pragma unroll
    for (int mt = 0; mt < 4; mt++) {
        #pragma unroll
        for (int nt = 0; nt < 4; nt++) {
            int n = n0 + wn0 + nt*8 + 2*t;
            #pragma unroll
            for (int half = 0; half < 2; half++) {
                int m = m0 + wm0 + mt*16 + g + half*8;
                float v0 = acc[mt][nt][half*2 + 0];
                float v1 = acc[mt][nt][half*2 + 1];
                if (bias) { v0 += bias[n]; v1 += bias[n+1]; }
                if (act)  { v0 *= normcdff(v0); v1 *= normcdff(v1); }
                if (res)  { v0 += res[(size_t)m*Nout + n];
                            v1 += res[(size_t)m*Nout + n + 1]; }
                *(float2*)(Y + (size_t)m*Nout + n) = make_float2(v0, v1);
            }
        }
    }
}

// ---------------------------------------------------------------------------
// Flash attention (tf32 mma, online softmax in registers).
// Block = (b, h, 256-query tile), 8 warps; warp owns 32 query rows (2 m-tiles).
// Key chunks of 64. P fragment re-layout (acc cols {2t,2t+1} -> A cols {t,t+4})
// done with intra-quad shuffles; V stored transposed (dh-major) in smem so
// B-fragment loads are conflict-free (stride 68 == 4 mod 32).
// qkv layout: (b*N+n)*768 + s*256 + h*32 + d
// ---------------------------------------------------------------------------
#define FQT  256
#define FKC  64
#define QSTR 36
#define VSTR 68
#define FSMEM ((FQT*QSTR + FKC*QSTR + 32*VSTR)*4)

__global__ __launch_bounds__(256) void flash_tc(
    const float* __restrict__ qkv, float* __restrict__ out)
{
    extern __shared__ float sm[];
    float* q_s = sm;                    // FQT x 36
    float* k_s = sm + FQT*QSTR;         // FKC x 36
    float* v_s = k_s + FKC*QSTR;        // 32 x 68 (transposed: [dh][key])

    int tid  = threadIdx.x;
    int warp = tid >> 5, lane = tid & 31;
    int g = lane >> 2, t = lane & 3;
    int b = blockIdx.z, h = blockIdx.y;
    int q0 = blockIdx.x * FQT;
    const float* qb = qkv + (size_t)b*N_*768 + h*32;
    const float scale = 0.17677669529663687f;   // 32^-0.5 (folded into Q)

    // load Q tile (256 x 32), pre-scaled + tf32-rounded
    for (int ii = tid; ii < FQT*8; ii += 256) {
        int r = ii >> 3, c4 = (ii & 7) << 2;
        float4 v = *(const float4*)(qb + (size_t)(q0+r)*768 + c4);
        q_s[r*QSTR + c4 + 0] = tf32r(v.x*scale);
        q_s[r*QSTR + c4 + 1] = tf32r(v.y*scale);
        q_s[r*QSTR + c4 + 2] = tf32r(v.z*scale);
        q_s[r*QSTR + c4 + 3] = tf32r(v.w*scale);
    }

    int row0 = warp * 32;
    float oa[2][4][4];
    float mrun[2][2], lrun[2][2];
    #pragma unroll
    for (int mt = 0; mt < 2; mt++) {
        mrun[mt][0] = -1e30f; mrun[mt][1] = -1e30f;
        lrun[mt][0] = 0.f;    lrun[mt][1] = 0.f;
        #pragma unroll
        for (int nt = 0; nt < 4; nt++)
            #pragma unroll
            for (int c = 0; c < 4; c++) oa[mt][nt][c] = 0.f;
    }

    int src_lo = (lane & ~3) | (t >> 1);
    int src_hi = src_lo | 2;

    for (int kt = 0; kt < N_; kt += FKC) {
        __syncthreads();   // prev chunk's K/V reads done (and Q stores on iter 0)
        for (int ii = tid; ii < FKC*8; ii += 256) {
            int r = ii >> 3, c4 = (ii & 7) << 2;
            float4 kv = *(const float4*)(qb + (size_t)(kt+r)*768 + 256 + c4);
            k_s[r*QSTR + c4 + 0] = tf32r(kv.x);
            k_s[r*QSTR + c4 + 1] = tf32r(kv.y);
            k_s[r*QSTR + c4 + 2] = tf32r(kv.z);
            k_s[r*QSTR + c4 + 3] = tf32r(kv.w);
            float4 vv = *(const float4*)(qb + (size_t)(kt+r)*768 + 512 + c4);
            v_s[(c4+0)*VSTR + r] = tf32r(vv.x);
            v_s[(c4+1)*VSTR + r] = tf32r(vv.y);
            v_s[(c4+2)*VSTR + r] = tf32r(vv.z);
            v_s[(c4+3)*VSTR + r] = tf32r(vv.w);
        }
        __syncthreads();

        // ---- S = Q @ K^T (pre-scaled) ----
        float s[2][8][4];
        #pragma unroll
        for (int mt = 0; mt < 2; mt++)
            #pragma unroll
            for (int nt = 0; nt < 8; nt++)
                #pragma unroll
                for (int c = 0; c < 4; c++) s[mt][nt][c] = 0.f;

        #pragma unroll
        for (int ks = 0; ks < 4; ks++) {
            int kc = ks*8 + t;
            u32 a[2][4];
            #pragma unroll
            for (int mt = 0; mt < 2; mt++) {
                int r = row0 + mt*16 + g;
                a[mt][0] = __float_as_uint(q_s[r*QSTR     + kc]);
                a[mt][1] = __float_as_uint(q_s[(r+8)*QSTR + kc]);
                a[mt][2] = __float_as_uint(q_s[r*QSTR     + kc + 4]);
                a[mt][3] = __float_as_uint(q_s[(r+8)*QSTR + kc + 4]);
            }
            u32 bb[8][2];
            #pragma unroll
            for (int nt = 0; nt < 8; nt++) {
                int rr = nt*8 + g;
                bb[nt][0] = __float_as_uint(k_s[rr*QSTR + kc]);
                bb[nt][1] = __float_as_uint(k_s[rr*QSTR + kc + 4]);
            }
            #pragma unroll
            for (int mt = 0; mt < 2; mt++)
                #pragma unroll
                for (int nt = 0; nt < 8; nt++)
                    mma_tf32(s[mt][nt], a[mt], bb[nt]);
        }

        // ---- online softmax (rows: mt*16+g -> c0,c1 ; +8 -> c2,c3) ----
        #pragma unroll
        for (int mt = 0; mt < 2; mt++) {
            float m0 = -1e30f, m1 = -1e30f;
            #pragma unroll
            for (int nt = 0; nt < 8; nt++) {
                m0 = fmaxf(m0, fmaxf(s[mt][nt][0], s[mt][nt][1]));
                m1 = fmaxf(m1, fmaxf(s[mt][nt][2], s[mt][nt][3]));
            }
            #pragma unroll
            for (int o = 1; o <= 2; o <<= 1) {
                m0 = fmaxf(m0, __shfl_xor_sync(0xffffffffu, m0, o));
                m1 = fmaxf(m1, __shfl_xor_sync(0xffffffffu, m1, o));
            }
            float mn0 = fmaxf(mrun[mt][0], m0);
            float mn1 = fmaxf(mrun[mt][1], m1);
            float sf0 = __expf(mrun[mt][0] - mn0);
            float sf1 = __expf(mrun[mt][1] - mn1);
            mrun[mt][0] = mn0; mrun[mt][1] = mn1;
            float ls0 = 0.f, ls1 = 0.f;
            #pragma unroll
            for (int nt = 0; nt < 8; nt++) {
                float e0 = __expf(s[mt][nt][0] - mn0);
                float e1 = __expf(s[mt][nt][1] - mn0);
                float e2 = __expf(s[mt][nt][2] - mn1);
                float e3 = __expf(s[mt][nt][3] - mn1);
                ls0 += e0 + e1;  ls1 += e2 + e3;
                s[mt][nt][0] = tf32r(e0);  s[mt][nt][1] = tf32r(e1);
                s[mt][nt][2] = tf32r(e2);  s[mt][nt][3] = tf32r(e3);
            }
            #pragma unroll
            for (int o = 1; o <= 2; o <<= 1) {
                ls0 += __shfl_xor_sync(0xffffffffu, ls0, o);
                ls1 += __shfl_xor_sync(0xffffffffu, ls1, o);
            }
            lrun[mt][0] = lrun[mt][0]*sf0 + ls0;
            lrun[mt][1] = lrun[mt][1]*sf1 + ls1;
            #pragma unroll
            for (int nt = 0; nt < 4; nt++) {
                oa[mt][nt][0] *= sf0;  oa[mt][nt][1] *= sf0;
                oa[mt][nt][2] *= sf1;  oa[mt][nt][3] *= sf1;
            }
        }

        // ---- O += P @ V : shuffle P from acc layout into A-frag layout ----
        #pragma unroll
        for (int k8 = 0; k8 < 8; k8++) {
            u32 a[2][4];
            #pragma unroll
            for (int mt = 0; mt < 2; mt++) {
                float y00 = __shfl_sync(0xffffffffu, s[mt][k8][0], src_lo);
                float y01 = __shfl_sync(0xffffffffu, s[mt][k8][1], src_lo);
                float y10 = __shfl_sync(0xffffffffu, s[mt][k8][0], src_hi);
                float y11 = __shfl_sync(0xffffffffu, s[mt][k8][1], src_hi);
                a[mt][0] = __float_as_uint((t & 1) ? y01 : y00);
                a[mt][2] = __float_as_uint((t & 1) ? y11 : y10);
                float z00 = __shfl_sync(0xffffffffu, s[mt][k8][2], src_lo);
                float z01 = __shfl_sync(0xffffffffu, s[mt][k8][3], src_lo);
                float z10 = __shfl_sync(0xffffffffu, s[mt][k8][2], src_hi);
                float z11 = __shfl_sync(0xffffffffu, s[mt][k8][3], src_hi);
                a[mt][1] = __float_as_uint((t & 1) ? z01 : z00);
                a[mt][3] = __float_as_uint((t & 1) ? z11 : z10);
            }
            u32 bb[4][2];
            #pragma unroll
            for (int nt = 0; nt < 4; nt++) {
                int d = nt*8 + g;
                bb[nt][0] = __float_as_uint(v_s[d*VSTR + k8*8 + t]);
                bb[nt][1] = __float_as_uint(v_s[d*VSTR + k8*8 + t + 4]);
            }
            #pragma unroll
            for (int mt = 0; mt < 2; mt++)
                #pragma unroll
                for (int nt = 0; nt < 4; nt++)
                    mma_tf32(oa[mt][nt], a[mt], bb[nt]);
        }
    }

    // ---- finalize: divide by l, write out ----
    #pragma unroll
    for (int mt = 0; mt < 2; mt++) {
        float i0 = 1.f / lrun[mt][0];
        float i1 = 1.f / lrun[mt][1];
        int r = q0 + row0 + mt*16 + g;
        #pragma unroll
        for (int nt = 0; nt < 4; nt++) {
            int col = h*32 + nt*8 + 2*t;
            *(float2*)(out + ((size_t)b*N_ + r)*C_ + col) =
                make_float2(oa[mt][nt][0]*i0, oa[mt][nt][1]*i0);
            *(float2*)(out + ((size_t)b*N_ + r + 8)*C_ + col) =
                make_float2(oa[mt][nt][2]*i1, oa[mt][nt][3]*i1);
        }
    }
}

// ---------------------------------------------------------------------------
// Deformable gather: one warp per (b, n, head); lane = channel d.
// ---------------------------------------------------------------------------
__global__ __launch_bounds__(128) void deform_kernel(
    const float* __restrict__ ref, const float* __restrict__ off,
    const float* __restrict__ awl, const float* __restrict__ vp,
    float* __restrict__ out)
{
    int u = (blockIdx.x << 2) + (threadIdx.x >> 5);
    int lane = threadIdx.x & 31;
    int h  = u & 7;
    int bn = u >> 3;
    int b  = bn >> 10;

    float rx = ref[(size_t)bn*2 + 0]*32.f - 0.5f;
    float ry = ref[(size_t)bn*2 + 1]*32.f - 0.5f;
    const float* offp = off + (size_t)bn*64 + h*8;
    const float* awp  = awl + (size_t)bn*32 + h*4;

    float a0 = awp[0], a1 = awp[1], a2 = awp[2], a3 = awp[3];
    float mx = fmaxf(fmaxf(a0,a1), fmaxf(a2,a3));
    float e0 = __expf(a0-mx), e1 = __expf(a1-mx), e2 = __expf(a2-mx), e3 = __expf(a3-mx);
    float inv = 1.f/(e0+e1+e2+e3);
    float aw4[4] = {e0*inv, e1*inv, e2*inv, e3*inv};

    const float* vb = vp + (size_t)b*N_*C_ + h*32 + lane;
    float acc = 0.f;
    #pragma unroll
    for (int p = 0; p < 4; p++) {
        float gx = rx + offp[p*2+0];
        float gy = ry + offp[p*2+1];
        float x0f = floorf(gx), y0f = floorf(gy);
        float lx = gx - x0f, ly = gy - y0f;
        int x0 = (int)x0f, y0 = (int)y0f;
        float s = 0.f;
        #pragma unroll
        for (int cy = 0; cy < 2; cy++) {
            int yi = y0 + cy;
            float wy = cy ? ly : (1.f - ly);
            bool vy = (yi >= 0) && (yi < 32);
            int yc = min(max(yi, 0), 31);
            #pragma unroll
            for (int cx = 0; cx < 2; cx++) {
                int xi = x0 + cx;
                float wx = cx ? lx : (1.f - lx);
                bool vx = (xi >= 0) && (xi < 32);
                int xc = min(max(xi, 0), 31);
                float val = (vx && vy) ? vb[(size_t)(yc*32 + xc)*C_] : 0.f;
                s = fmaf(val, wx*wy, s);
            }
        }
        acc = fmaf(aw4[p], s, acc);
    }
    out[(size_t)bn*C_ + h*32 + lane] = acc;
}

// ---------------------------------------------------------------------------
// Launch
// ---------------------------------------------------------------------------
extern "C" void kernel_launch(void* const* d_in, const int* in_sizes, int n_in,
                              void* d_out, int out_size)
{
    const float* x       = (const float*)d_in[0];
    const float* ref     = (const float*)d_in[1];
    const float* value   = (const float*)d_in[2];
    const float* ln1w    = (const float*)d_in[3];
    const float* ln1b    = (const float*)d_in[4];
    const float* ln2w    = (const float*)d_in[5];
    const float* ln2b    = (const float*)d_in[6];
    const float* ln3w    = (const float*)d_in[7];
    const float* ln3b    = (const float*)d_in[8];
    const float* qkv_w   = (const float*)d_in[9];
    const float* proj_w  = (const float*)d_in[10];
    const float* proj_b  = (const float*)d_in[11];
    const float* off_w   = (const float*)d_in[12];
    const float* off_b   = (const float*)d_in[13];
    const float* aw_w    = (const float*)d_in[14];
    const float* aw_b    = (const float*)d_in[15];
    const float* vproj_w = (const float*)d_in[16];
    const float* vproj_b = (const float*)d_in[17];
    const float* oproj_w = (const float*)d_in[18];
    const float* oproj_b = (const float*)d_in[19];
    const float* fc1_w   = (const float*)d_in[20];
    const float* fc1_b   = (const float*)d_in[21];
    const float* fc2_w   = (const float*)d_in[22];
    const float* fc2_b   = (const float*)d_in[23];
    float* out = (float*)d_out;

    float *y, *qkvb, *tmp, *x2, *offb, *awb, *vpb, *h1;
    cudaGetSymbolAddress((void**)&y,    g_y);
    cudaGetSymbolAddress((void**)&qkvb, g_qkv);
    cudaGetSymbolAddress((void**)&tmp,  g_tmp);
    cudaGetSymbolAddress((void**)&x2,   g_x2);
    cudaGetSymbolAddress((void**)&offb, g_off);
    cudaGetSymbolAddress((void**)&awb,  g_awl);
    cudaGetSymbolAddress((void**)&vpb,  g_vp);
    cudaGetSymbolAddress((void**)&h1,   g_h1);

    cudaFuncSetAttribute(flash_tc,
        cudaFuncAttributeMaxDynamicSharedMemorySize, FSMEM);

    // x1 = x + attn(ln1(x))
    ln_kernel<<<M_, 256>>>(x, ln1w, ln1b, y);
    gemm_tc<<<dim3(6,128), 256>>>(y, qkv_w, nullptr, nullptr, qkvb, M_, 768, 256, 0);
    flash_tc<<<dim3(N_/FQT, NH_, B_), 256, FSMEM>>>(qkvb, tmp);
    gemm_tc<<<dim3(2,128), 256>>>(tmp, proj_w, proj_b, x, x2, M_, 256, 256, 0);

    // x2 = x1 + deform(ln2(x1))
    ln_kernel<<<M_, 256>>>(x2, ln2w, ln2b, y);
    gemm_kernel<<<dim3(1,128), 256>>>(y, off_w, off_b, nullptr, offb, M_, 64, 256, 0);
    gemm_kernel<<<dim3(1,128), 256>>>(y, aw_w,  aw_b,  nullptr, awb,  M_, 32, 256, 0);
    gemm_tc<<<dim3(2,128), 256>>>(value, vproj_w, vproj_b, nullptr, vpb, M_, 256, 256, 0);
    deform_kernel<<<32768, 128>>>(ref, offb, awb, vpb, tmp);
    gemm_tc<<<dim3(2,128), 256>>>(tmp, oproj_w, oproj_b, x2, x2, M_, 256, 256, 0);

    // out = x2 + fc2(gelu(fc1(ln3(x2))))
    ln_kernel<<<M_, 256>>>(x2, ln3w, ln3b, y);
    gemm_tc<<<dim3(8,128), 256>>>(y, fc1_w, fc1_b, nullptr, h1, M_, 1024, 256, 1);
    gemm_tc<<<dim3(2,128), 256>>>(h1, fc2_w, fc2_b, x2, out, M_, 256, 1024, 0);
}

// round 7
// speedup vs baseline: 3.9017x; 1.1931x over previous
#include <cuda_runtime.h>
#include <cstdint>
#include <math.h>

typedef unsigned int u32;

// Problem constants
#define B_  16
#define N_  1024
#define C_  256
#define NH_ 8
#define DH_ 32
#define M_  (B_*N_)      // 16384 rows
#define HID_ 1024

// ---------------------------------------------------------------------------
// Scratch (static __device__ arrays; no allocations allowed)
// ---------------------------------------------------------------------------
__device__ float g_y  [M_*C_];
__device__ float g_qkv[M_*3*C_];
__device__ float g_tmp[M_*C_];
__device__ float g_x2 [M_*C_];
__device__ float g_off[M_*64];
__device__ float g_awl[M_*32];
__device__ float g_vp [M_*C_];
__device__ float g_h1 [M_*HID_];

// ---------------------------------------------------------------------------
// tf32 helpers
// ---------------------------------------------------------------------------
__device__ __forceinline__ float tf32r(float x) {
    u32 u;
    asm("cvt.rna.tf32.f32 %0, %1;" : "=r"(u) : "f"(x));
    return __uint_as_float(u);
}

__device__ __forceinline__ void mma_tf32(float (&d)[4],
                                         const u32 (&a)[4],
                                         const u32 (&b)[2]) {
    asm volatile(
        "mma.sync.aligned.m16n8k8.row.col.f32.tf32.tf32.f32 "
        "{%0,%1,%2,%3}, {%4,%5,%6,%7}, {%8,%9}, {%0,%1,%2,%3};"
        : "+f"(d[0]), "+f"(d[1]), "+f"(d[2]), "+f"(d[3])
        : "r"(a[0]), "r"(a[1]), "r"(a[2]), "r"(a[3]),
          "r"(b[0]), "r"(b[1]));
}

// ---------------------------------------------------------------------------
// LayerNorm: one block per row, 256 threads (C=256)
// ---------------------------------------------------------------------------
__global__ __launch_bounds__(256) void ln_kernel(
    const float* __restrict__ in, const float* __restrict__ w,
    const float* __restrict__ b, float* __restrict__ out)
{
    __shared__ float red[8];
    int row = blockIdx.x;
    int t = threadIdx.x;
    float v = in[(size_t)row*C_ + t];
    float s = v;
    #pragma unroll
    for (int o = 16; o; o >>= 1) s += __shfl_xor_sync(0xffffffffu, s, o);
    if ((t & 31) == 0) red[t >> 5] = s;
    __syncthreads();
    float tot = 0.f;
    #pragma unroll
    for (int i = 0; i < 8; i++) tot += red[i];
    float mean = tot * (1.0f/256.0f);
    __syncthreads();
    float d = v - mean;
    s = d*d;
    #pragma unroll
    for (int o = 16; o; o >>= 1) s += __shfl_xor_sync(0xffffffffu, s, o);
    if ((t & 31) == 0) red[t >> 5] = s;
    __syncthreads();
    tot = 0.f;
    #pragma unroll
    for (int i = 0; i < 8; i++) tot += red[i];
    float rs = rsqrtf(tot*(1.0f/256.0f) + 1e-5f);
    out[(size_t)row*C_ + t] = d*rs*w[t] + b[t];
}

// ---------------------------------------------------------------------------
// tf32 tensor-core GEMM: Y[M,Nout] = X[M,K] @ W[Nout,K]^T (+bias)(+gelu)(+res)
// Block 128x128, BK=32, 8 warps in 2x4; warp tile 64x32 = 4 m16 x 4 n8 tiles.
// smem stride 36 (== 4 mod 32) makes every fragment LDS conflict-free.
// PAD!=0 build handles Nout not multiple of 128 (guarded W loads + stores).
// ---------------------------------------------------------------------------
#define TSTR 36

template <int PAD>
__global__ __launch_bounds__(256) void gemm_tc_t(
    const float* __restrict__ X, const float* __restrict__ W,
    const float* __restrict__ bias, const float* __restrict__ res,
    float* __restrict__ Y, int M, int Nout, int K, int act)
{
    __shared__ float sX[128*TSTR];
    __shared__ float sW[128*TSTR];
    int tid  = threadIdx.x;
    int warp = tid >> 5, lane = tid & 31;
    int g = lane >> 2, t = lane & 3;
    int wm0 = (warp >> 2) * 64;
    int wn0 = (warp & 3) * 32;
    int m0 = blockIdx.y * 128, n0 = blockIdx.x * 128;

    float acc[4][4][4];
    #pragma unroll
    for (int mt = 0; mt < 4; mt++)
        #pragma unroll
        for (int nt = 0; nt < 4; nt++)
            #pragma unroll
            for (int c = 0; c < 4; c++) acc[mt][nt][c] = 0.f;

    for (int k0 = 0; k0 < K; k0 += 32) {
        #pragma unroll
        for (int i = 0; i < 4; i++) {
            int idx = tid + (i << 8);
            int r  = idx >> 3;
            int c4 = (idx & 7) << 2;
            float4 xv = *(const float4*)(X + (size_t)(m0+r)*K + k0 + c4);
            sX[r*TSTR + c4 + 0] = tf32r(xv.x);
            sX[r*TSTR + c4 + 1] = tf32r(xv.y);
            sX[r*TSTR + c4 + 2] = tf32r(xv.z);
            sX[r*TSTR + c4 + 3] = tf32r(xv.w);
            float4 wv = make_float4(0.f, 0.f, 0.f, 0.f);
            if (!PAD || (n0 + r < Nout))
                wv = *(const float4*)(W + (size_t)(n0+r)*K + k0 + c4);
            sW[r*TSTR + c4 + 0] = tf32r(wv.x);
            sW[r*TSTR + c4 + 1] = tf32r(wv.y);
            sW[r*TSTR + c4 + 2] = tf32r(wv.z);
            sW[r*TSTR + c4 + 3] = tf32r(wv.w);
        }
        __syncthreads();
        #pragma unroll
        for (int ks = 0; ks < 4; ks++) {
            int kc = ks*8 + t;
            u32 a[4][4];
            #pragma unroll
            for (int mt = 0; mt < 4; mt++) {
                int r = wm0 + mt*16 + g;
                a[mt][0] = __float_as_uint(sX[r*TSTR     + kc]);
                a[mt][1] = __float_as_uint(sX[(r+8)*TSTR + kc]);
                a[mt][2] = __float_as_uint(sX[r*TSTR     + kc + 4]);
                a[mt][3] = __float_as_uint(sX[(r+8)*TSTR + kc + 4]);
            }
            u32 bb[4][2];
            #pragma unroll
            for (int nt = 0; nt < 4; nt++) {
                int r = wn0 + nt*8 + g;
                bb[nt][0] = __float_as_uint(sW[r*TSTR + kc]);
                bb[nt][1] = __float_as_uint(sW[r*TSTR + kc + 4]);
            }
            #pragma unroll
            for (int mt = 0; mt < 4; mt++)
                #pragma unroll
                for (int nt = 0; nt < 4; nt++)
                    mma_tf32(acc[mt][nt], a[mt], bb[nt]);
        }
        __syncthreads();
    }

    #pragma unroll
    for (int mt = 0; mt < 4; mt++) {
        #pragma unroll
        for (int nt = 0; nt < 4; nt++) {
            int n = n0 + wn0 + nt*8 + 2*t;
            if (PAD && n >= Nout) continue;
            #pragma unroll
            for (int half = 0; half < 2; half++) {
                int m = m0 + wm0 + mt*16 + g + half*8;
                float v0 = acc[mt][nt][half*2 + 0];
                float v1 = acc[mt][nt][half*2 + 1];
                if (bias) { v0 += bias[n]; v1 += bias[n+1]; }
                if (act)  { v0 *= normcdff(v0); v1 *= normcdff(v1); }
                if (res)  { v0 += res[(size_t)m*Nout + n];
                            v1 += res[(size_t)m*Nout + n + 1]; }
                *(float2*)(Y + (size_t)m*Nout + n) = make_float2(v0, v1);
            }
        }
    }
}

// ---------------------------------------------------------------------------
// Flash attention v2 (tf32 mma, online softmax in registers).
// Block = (b, h, 128-query tile), 8 warps; warp owns 16 query rows (1 m-tile).
// 64-key chunks, K/V prefetched into registers one chunk ahead so the LDG
// latency overlaps the previous chunk's compute. ~105 regs -> 2 CTAs/SM.
// P re-layout (acc cols {2t,2t+1} -> A cols {t,t+4}) via intra-quad shuffles.
// qkv layout: (b*N+n)*768 + s*256 + h*32 + d
// ---------------------------------------------------------------------------
#define FQT  128
#define FKC  64
#define QSTR 36
#define VSTR 68
#define FSMEM ((FQT*QSTR + FKC*QSTR + 32*VSTR)*4)

__global__ __launch_bounds__(256) void flash_tc(
    const float* __restrict__ qkv, float* __restrict__ out)
{
    extern __shared__ float sm[];
    float* q_s = sm;                    // FQT x 36
    float* k_s = sm + FQT*QSTR;         // FKC x 36
    float* v_s = k_s + FKC*QSTR;        // 32 x 68 (transposed: [dh][key])

    int tid  = threadIdx.x;
    int warp = tid >> 5, lane = tid & 31;
    int g = lane >> 2, t = lane & 3;
    int b = blockIdx.z, h = blockIdx.y;
    int q0 = blockIdx.x * FQT;
    const float* qb = qkv + (size_t)b*N_*768 + h*32;
    const float scale = 0.17677669529663687f;   // 32^-0.5 (folded into Q)

    // load Q tile (128 x 32), pre-scaled + tf32-rounded
    for (int ii = tid; ii < FQT*8; ii += 256) {
        int r = ii >> 3, c4 = (ii & 7) << 2;
        float4 v = *(const float4*)(qb + (size_t)(q0+r)*768 + c4);
        q_s[r*QSTR + c4 + 0] = tf32r(v.x*scale);
        q_s[r*QSTR + c4 + 1] = tf32r(v.y*scale);
        q_s[r*QSTR + c4 + 2] = tf32r(v.z*scale);
        q_s[r*QSTR + c4 + 3] = tf32r(v.w*scale);
    }

    int row0 = warp * 16;
    float oa[4][4];
    #pragma unroll
    for (int nt = 0; nt < 4; nt++)
        #pragma unroll
        for (int c = 0; c < 4; c++) oa[nt][c] = 0.f;
    float mr0 = -1e30f, mr1 = -1e30f, lr0 = 0.f, lr1 = 0.f;

    int src_lo = (lane & ~3) | (t >> 1);
    int src_hi = src_lo | 2;

    // staging indices: thread covers rows rA (0..31) and rB (32..63)
    int rA = tid >> 3, rB = rA + 32;
    int c4 = (tid & 7) << 2;

    // prefetch chunk 0
    float4 kfA = *(const float4*)(qb + (size_t)rA*768 + 256 + c4);
    float4 kfB = *(const float4*)(qb + (size_t)rB*768 + 256 + c4);
    float4 vfA = *(const float4*)(qb + (size_t)rA*768 + 512 + c4);
    float4 vfB = *(const float4*)(qb + (size_t)rB*768 + 512 + c4);

    for (int kt = 0; kt < N_; kt += FKC) {
        __syncthreads();   // prev chunk's smem reads done (and Q stores, iter 0)
        k_s[rA*QSTR + c4 + 0] = tf32r(kfA.x);
        k_s[rA*QSTR + c4 + 1] = tf32r(kfA.y);
        k_s[rA*QSTR + c4 + 2] = tf32r(kfA.z);
        k_s[rA*QSTR + c4 + 3] = tf32r(kfA.w);
        k_s[rB*QSTR + c4 + 0] = tf32r(kfB.x);
        k_s[rB*QSTR + c4 + 1] = tf32r(kfB.y);
        k_s[rB*QSTR + c4 + 2] = tf32r(kfB.z);
        k_s[rB*QSTR + c4 + 3] = tf32r(kfB.w);
        v_s[(c4+0)*VSTR + rA] = tf32r(vfA.x);
        v_s[(c4+1)*VSTR + rA] = tf32r(vfA.y);
        v_s[(c4+2)*VSTR + rA] = tf32r(vfA.z);
        v_s[(c4+3)*VSTR + rA] = tf32r(vfA.w);
        v_s[(c4+0)*VSTR + rB] = tf32r(vfB.x);
        v_s[(c4+1)*VSTR + rB] = tf32r(vfB.y);
        v_s[(c4+2)*VSTR + rB] = tf32r(vfB.z);
        v_s[(c4+3)*VSTR + rB] = tf32r(vfB.w);
        __syncthreads();

        // prefetch next chunk (overlaps compute below)
        int ktn = kt + FKC;
        if (ktn < N_) {
            kfA = *(const float4*)(qb + (size_t)(ktn+rA)*768 + 256 + c4);
            kfB = *(const float4*)(qb + (size_t)(ktn+rB)*768 + 256 + c4);
            vfA = *(const float4*)(qb + (size_t)(ktn+rA)*768 + 512 + c4);
            vfB = *(const float4*)(qb + (size_t)(ktn+rB)*768 + 512 + c4);
        }

        // ---- S = Q @ K^T (pre-scaled) ----
        float s[8][4];
        #pragma unroll
        for (int nt = 0; nt < 8; nt++)
            #pragma unroll
            for (int c = 0; c < 4; c++) s[nt][c] = 0.f;

        #pragma unroll
        for (int ks = 0; ks < 4; ks++) {
            int kc = ks*8 + t;
            u32 a[4];
            a[0] = __float_as_uint(q_s[(row0+g)*QSTR   + kc]);
            a[1] = __float_as_uint(q_s[(row0+8+g)*QSTR + kc]);
            a[2] = __float_as_uint(q_s[(row0+g)*QSTR   + kc + 4]);
            a[3] = __float_as_uint(q_s[(row0+8+g)*QSTR + kc + 4]);
            u32 bb[8][2];
            #pragma unroll
            for (int nt = 0; nt < 8; nt++) {
                int rr = nt*8 + g;
                bb[nt][0] = __float_as_uint(k_s[rr*QSTR + kc]);
                bb[nt][1] = __float_as_uint(k_s[rr*QSTR + kc + 4]);
            }
            #pragma unroll
            for (int nt = 0; nt < 8; nt++)
                mma_tf32(s[nt], a, bb[nt]);
        }

        // ---- online softmax (row g -> c0,c1 ; row g+8 -> c2,c3) ----
        {
            float m0 = -1e30f, m1 = -1e30f;
            #pragma unroll
            for (int nt = 0; nt < 8; nt++) {
                m0 = fmaxf(m0, fmaxf(s[nt][0], s[nt][1]));
                m1 = fmaxf(m1, fmaxf(s[nt][2], s[nt][3]));
            }
            #pragma unroll
            for (int o = 1; o <= 2; o <<= 1) {
                m0 = fmaxf(m0, __shfl_xor_sync(0xffffffffu, m0, o));
                m1 = fmaxf(m1, __shfl_xor_sync(0xffffffffu, m1, o));
            }
            float mn0 = fmaxf(mr0, m0);
            float mn1 = fmaxf(mr1, m1);
            float sf0 = __expf(mr0 - mn0);
            float sf1 = __expf(mr1 - mn1);
            mr0 = mn0; mr1 = mn1;
            float ls0 = 0.f, ls1 = 0.f;
            #pragma unroll
            for (int nt = 0; nt < 8; nt++) {
                float e0 = __expf(s[nt][0] - mn0);
                float e1 = __expf(s[nt][1] - mn0);
                float e2 = __expf(s[nt][2] - mn1);
                float e3 = __expf(s[nt][3] - mn1);
                ls0 += e0 + e1;  ls1 += e2 + e3;
                s[nt][0] = tf32r(e0);  s[nt][1] = tf32r(e1);
                s[nt][2] = tf32r(e2);  s[nt][3] = tf32r(e3);
            }
            #pragma unroll
            for (int o = 1; o <= 2; o <<= 1) {
                ls0 += __shfl_xor_sync(0xffffffffu, ls0, o);
                ls1 += __shfl_xor_sync(0xffffffffu, ls1, o);
            }
            lr0 = lr0*sf0 + ls0;
            lr1 = lr1*sf1 + ls1;
            #pragma unroll
            for (int nt = 0; nt < 4; nt++) {
                oa[nt][0] *= sf0;  oa[nt][1] *= sf0;
                oa[nt][2] *= sf1;  oa[nt][3] *= sf1;
            }
        }

        // ---- O += P @ V : shuffle P from acc layout into A-frag layout ----
        #pragma unroll
        for (int k8 = 0; k8 < 8; k8++) {
            float y00 = __shfl_sync(0xffffffffu, s[k8][0], src_lo);
            float y01 = __shfl_sync(0xffffffffu, s[k8][1], src_lo);
            float y10 = __shfl_sync(0xffffffffu, s[k8][0], src_hi);
            float y11 = __shfl_sync(0xffffffffu, s[k8][1], src_hi);
            float z00 = __shfl_sync(0xffffffffu, s[k8][2], src_lo);
            float z01 = __shfl_sync(0xffffffffu, s[k8][3], src_lo);
            float z10 = __shfl_sync(0xffffffffu, s[k8][2], src_hi);
            float z11 = __shfl_sync(0xffffffffu, s[k8][3], src_hi);
            u32 a[4];
            a[0] = __float_as_uint((t & 1) ? y01 : y00);
            a[2] = __float_as_uint((t & 1) ? y11 : y10);
            a[1] = __float_as_uint((t & 1) ? z01 : z00);
            a[3] = __float_as_uint((t & 1) ? z11 : z10);
            u32 bb[4][2];
            #pragma unroll
            for (int nt = 0; nt < 4; nt++) {
                int d = nt*8 + g;
                bb[nt][0] = __float_as_uint(v_s[d*VSTR + k8*8 + t]);
                bb[nt][1] = __float_as_uint(v_s[d*VSTR + k8*8 + t + 4]);
            }
            #pragma unroll
            for (int nt = 0; nt < 4; nt++)
                mma_tf32(oa[nt], a, bb[nt]);
        }
    }

    // ---- finalize: divide by l, write out ----
    float i0 = 1.f / lr0;
    float i1 = 1.f / lr1;
    int r = q0 + row0 + g;
    #pragma unroll
    for (int nt = 0; nt < 4; nt++) {
        int col = h*32 + nt*8 + 2*t;
        *(float2*)(out + ((size_t)b*N_ + r)*C_ + col) =
            make_float2(oa[nt][0]*i0, oa[nt][1]*i0);
        *(float2*)(out + ((size_t)b*N_ + r + 8)*C_ + col) =
            make_float2(oa[nt][2]*i1, oa[nt][3]*i1);
    }
}

// ---------------------------------------------------------------------------
// Deformable gather: one warp per (b, n, head); lane = channel d.
// ---------------------------------------------------------------------------
__global__ __launch_bounds__(128) void deform_kernel(
    const float* __restrict__ ref, const float* __restrict__ off,
    const float* __restrict__ awl, const float* __restrict__ vp,
    float* __restrict__ out)
{
    int u = (blockIdx.x << 2) + (threadIdx.x >> 5);
    int lane = threadIdx.x & 31;
    int h  = u & 7;
    int bn = u >> 3;
    int b  = bn >> 10;

    float rx = ref[(size_t)bn*2 + 0]*32.f - 0.5f;
    float ry = ref[(size_t)bn*2 + 1]*32.f - 0.5f;
    const float* offp = off + (size_t)bn*64 + h*8;
    const float* awp  = awl + (size_t)bn*32 + h*4;

    float a0 = awp[0], a1 = awp[1], a2 = awp[2], a3 = awp[3];
    float mx = fmaxf(fmaxf(a0,a1), fmaxf(a2,a3));
    float e0 = __expf(a0-mx), e1 = __expf(a1-mx), e2 = __expf(a2-mx), e3 = __expf(a3-mx);
    float inv = 1.f/(e0+e1+e2+e3);
    float aw4[4] = {e0*inv, e1*inv, e2*inv, e3*inv};

    const float* vb = vp + (size_t)b*N_*C_ + h*32 + lane;
    float acc = 0.f;
    #pragma unroll
    for (int p = 0; p < 4; p++) {
        float gx = rx + offp[p*2+0];
        float gy = ry + offp[p*2+1];
        float x0f = floorf(gx), y0f = floorf(gy);
        float lx = gx - x0f, ly = gy - y0f;
        int x0 = (int)x0f, y0 = (int)y0f;
        float s = 0.f;
        #pragma unroll
        for (int cy = 0; cy < 2; cy++) {
            int yi = y0 + cy;
            float wy = cy ? ly : (1.f - ly);
            bool vy = (yi >= 0) && (yi < 32);
            int yc = min(max(yi, 0), 31);
            #pragma unroll
            for (int cx = 0; cx < 2; cx++) {
                int xi = x0 + cx;
                float wx = cx ? lx : (1.f - lx);
                bool vx = (xi >= 0) && (xi < 32);
                int xc = min(max(xi, 0), 31);
                float val = (vx && vy) ? vb[(size_t)(yc*32 + xc)*C_] : 0.f;
                s = fmaf(val, wx*wy, s);
            }
        }
        acc = fmaf(aw4[p], s, acc);
    }
    out[(size_t)bn*C_ + h*32 + lane] = acc;
}

// ---------------------------------------------------------------------------
// Launch
// ---------------------------------------------------------------------------
extern "C" void kernel_launch(void* const* d_in, const int* in_sizes, int n_in,
                              void* d_out, int out_size)
{
    const float* x       = (const float*)d_in[0];
    const float* ref     = (const float*)d_in[1];
    const float* value   = (const float*)d_in[2];
    const float* ln1w    = (const float*)d_in[3];
    const float* ln1b    = (const float*)d_in[4];
    const float* ln2w    = (const float*)d_in[5];
    const float* ln2b    = (const float*)d_in[6];
    const float* ln3w    = (const float*)d_in[7];
    const float* ln3b    = (const float*)d_in[8];
    const float* qkv_w   = (const float*)d_in[9];
    const float* proj_w  = (const float*)d_in[10];
    const float* proj_b  = (const float*)d_in[11];
    const float* off_w   = (const float*)d_in[12];
    const float* off_b   = (const float*)d_in[13];
    const float* aw_w    = (const float*)d_in[14];
    const float* aw_b    = (const float*)d_in[15];
    const float* vproj_w = (const float*)d_in[16];
    const float* vproj_b = (const float*)d_in[17];
    const float* oproj_w = (const float*)d_in[18];
    const float* oproj_b = (const float*)d_in[19];
    const float* fc1_w   = (const float*)d_in[20];
    const float* fc1_b   = (const float*)d_in[21];
    const float* fc2_w   = (const float*)d_in[22];
    const float* fc2_b   = (const float*)d_in[23];
    float* out = (float*)d_out;

    float *y, *qkvb, *tmp, *x2, *offb, *awb, *vpb, *h1;
    cudaGetSymbolAddress((void**)&y,    g_y);
    cudaGetSymbolAddress((void**)&qkvb, g_qkv);
    cudaGetSymbolAddress((void**)&tmp,  g_tmp);
    cudaGetSymbolAddress((void**)&x2,   g_x2);
    cudaGetSymbolAddress((void**)&offb, g_off);
    cudaGetSymbolAddress((void**)&awb,  g_awl);
    cudaGetSymbolAddress((void**)&vpb,  g_vp);
    cudaGetSymbolAddress((void**)&h1,   g_h1);

    cudaFuncSetAttribute(flash_tc,
        cudaFuncAttributeMaxDynamicSharedMemorySize, FSMEM);

    // x1 = x + attn(ln1(x))
    ln_kernel<<<M_, 256>>>(x, ln1w, ln1b, y);
    gemm_tc_t<0><<<dim3(6,128), 256>>>(y, qkv_w, nullptr, nullptr, qkvb, M_, 768, 256, 0);
    flash_tc<<<dim3(N_/FQT, NH_, B_), 256, FSMEM>>>(qkvb, tmp);
    gemm_tc_t<0><<<dim3(2,128), 256>>>(tmp, proj_w, proj_b, x, x2, M_, 256, 256, 0);

    // x2 = x1 + deform(ln2(x1))
    ln_kernel<<<M_, 256>>>(x2, ln2w, ln2b, y);
    gemm_tc_t<1><<<dim3(1,128), 256>>>(y, off_w, off_b, nullptr, offb, M_, 64, 256, 0);
    gemm_tc_t<1><<<dim3(1,128), 256>>>(y, aw_w,  aw_b,  nullptr, awb,  M_, 32, 256, 0);
    gemm_tc_t<0><<<dim3(2,128), 256>>>(value, vproj_w, vproj_b, nullptr, vpb, M_, 256, 256, 0);
    deform_kernel<<<32768, 128>>>(ref, offb, awb, vpb, tmp);
    gemm_tc_t<0><<<dim3(2,128), 256>>>(tmp, oproj_w, oproj_b, x2, x2, M_, 256, 256, 0);

    // out = x2 + fc2(gelu(fc1(ln3(x2))))
    ln_kernel<<<M_, 256>>>(x2, ln3w, ln3b, y);
    gemm_tc_t<0><<<dim3(8,128), 256>>>(y, fc1_w, fc1_b, nullptr, h1, M_, 1024, 256, 1);
    gemm_tc_t<0><<<dim3(2,128), 256>>>(h1, fc2_w, fc2_b, x2, out, M_, 256, 1024, 0);
}

// round 8
// speedup vs baseline: 3.9798x; 1.0200x over previous
#include <cuda_runtime.h>
#include <cstdint>
#include <math.h>

typedef unsigned int u32;

// Problem constants
#define B_  16
#define N_  1024
#define C_  256
#define NH_ 8
#define DH_ 32
#define M_  (B_*N_)      // 16384 rows
#define HID_ 1024

// ---------------------------------------------------------------------------
// Scratch (static __device__ arrays; no allocations allowed)
// ---------------------------------------------------------------------------
__device__ float g_y  [M_*C_];
__device__ float g_qkv[M_*3*C_];
__device__ float g_tmp[M_*C_];
__device__ float g_x2 [M_*C_];
__device__ float g_off[M_*64];
__device__ float g_awl[M_*32];
__device__ float g_vp [M_*C_];
__device__ float g_h1 [M_*HID_];

// ---------------------------------------------------------------------------
// tf32 helpers
// ---------------------------------------------------------------------------
__device__ __forceinline__ float tf32r(float x) {
    u32 u;
    asm("cvt.rna.tf32.f32 %0, %1;" : "=r"(u) : "f"(x));
    return __uint_as_float(u);
}

__device__ __forceinline__ void mma_tf32(float (&d)[4],
                                         const u32 (&a)[4],
                                         const u32 (&b)[2]) {
    asm volatile(
        "mma.sync.aligned.m16n8k8.row.col.f32.tf32.tf32.f32 "
        "{%0,%1,%2,%3}, {%4,%5,%6,%7}, {%8,%9}, {%0,%1,%2,%3};"
        : "+f"(d[0]), "+f"(d[1]), "+f"(d[2]), "+f"(d[3])
        : "r"(a[0]), "r"(a[1]), "r"(a[2]), "r"(a[3]),
          "r"(b[0]), "r"(b[1]));
}

__device__ __forceinline__ u32 smem_u32(const void* p) {
    return (u32)__cvta_generic_to_shared(p);
}

// ---------------------------------------------------------------------------
// LayerNorm: one block per row, 256 threads (C=256).
// Output is tf32-rounded (it is consumed only as a GEMM A-operand).
// ---------------------------------------------------------------------------
__global__ __launch_bounds__(256) void ln_kernel(
    const float* __restrict__ in, const float* __restrict__ w,
    const float* __restrict__ b, float* __restrict__ out)
{
    __shared__ float red[8];
    int row = blockIdx.x;
    int t = threadIdx.x;
    float v = in[(size_t)row*C_ + t];
    float s = v;
    #pragma unroll
    for (int o = 16; o; o >>= 1) s += __shfl_xor_sync(0xffffffffu, s, o);
    if ((t & 31) == 0) red[t >> 5] = s;
    __syncthreads();
    float tot = 0.f;
    #pragma unroll
    for (int i = 0; i < 8; i++) tot += red[i];
    float mean = tot * (1.0f/256.0f);
    __syncthreads();
    float d = v - mean;
    s = d*d;
    #pragma unroll
    for (int o = 16; o; o >>= 1) s += __shfl_xor_sync(0xffffffffu, s, o);
    if ((t & 31) == 0) red[t >> 5] = s;
    __syncthreads();
    tot = 0.f;
    #pragma unroll
    for (int i = 0; i < 8; i++) tot += red[i];
    float rs = rsqrtf(tot*(1.0f/256.0f) + 1e-5f);
    out[(size_t)row*C_ + t] = tf32r(d*rs*w[t] + b[t]);
}

// ---------------------------------------------------------------------------
// tf32 tensor-core GEMM, cp.async 2-stage double-buffered pipeline.
// Y[M,Nout] = X[M,K] @ W[Nout,K]^T (+bias)(+gelu)(+res)(+round)
// Block 128x128, BK=32, 8 warps in 2x4; warp tile 64x32.
// Operands land in smem as raw f32; the tf32 MMA truncates low bits (X is
// pre-rounded by its producer where it matters). Stride 36 = conflict-free.
// PAD: guards W rows/cols vs Nout. RND: tf32-round the output (fc1 -> fc2).
// ---------------------------------------------------------------------------
#define TSTR 36
#define GTILE (128*TSTR)              // floats per operand-stage
#define GSMEM (2*2*GTILE*4)           // 2 stages x (X,W) x 4B = 73728 B

template <int PAD, int RND>
__global__ __launch_bounds__(256) void gemm_tc_t(
    const float* __restrict__ X, const float* __restrict__ W,
    const float* __restrict__ bias, const float* __restrict__ res,
    float* __restrict__ Y, int M, int Nout, int K, int act)
{
    extern __shared__ float dsm[];
    int tid  = threadIdx.x;
    int warp = tid >> 5, lane = tid & 31;
    int g = lane >> 2, t = lane & 3;
    int wm0 = (warp >> 2) * 64;
    int wn0 = (warp & 3) * 32;
    int m0 = blockIdx.y * 128, n0 = blockIdx.x * 128;
    u32 sb = smem_u32(dsm);

    // issue one K-tile (stage s, k-offset k0) via cp.async
    auto issue_tile = [&](int s, int k0) {
        #pragma unroll
        for (int i = 0; i < 4; i++) {
            int idx = tid + (i << 8);
            int r  = idx >> 3;
            int c4 = (idx & 7) << 2;
            u32 dX = sb + (u32)((s*2*GTILE) + r*TSTR + c4)*4u;
            const float* gX = X + (size_t)(m0+r)*K + k0 + c4;
            asm volatile("cp.async.ca.shared.global [%0], [%1], 16;"
                         :: "r"(dX), "l"(gX));
            u32 dW = sb + (u32)((s*2*GTILE) + GTILE + r*TSTR + c4)*4u;
            const float* gW = W + (size_t)(n0+r)*K + k0 + c4;
            if (PAD) {
                int vld = (n0 + r < Nout) ? 16 : 0;
                asm volatile("cp.async.ca.shared.global [%0], [%1], 16, %2;"
                             :: "r"(dW), "l"(gW), "r"(vld));
            } else {
                asm volatile("cp.async.ca.shared.global [%0], [%1], 16;"
                             :: "r"(dW), "l"(gW));
            }
        }
    };

    float acc[4][4][4];
    #pragma unroll
    for (int mt = 0; mt < 4; mt++)
        #pragma unroll
        for (int nt = 0; nt < 4; nt++)
            #pragma unroll
            for (int c = 0; c < 4; c++) acc[mt][nt][c] = 0.f;

    issue_tile(0, 0);
    asm volatile("cp.async.commit_group;" ::: "memory");
    issue_tile(1, 32);
    asm volatile("cp.async.commit_group;" ::: "memory");

    int nk = K >> 5;
    for (int it = 0; it < nk; it++) {
        asm volatile("cp.async.wait_group 1;" ::: "memory");
        __syncthreads();

        const float* sX = dsm + (it & 1)*2*GTILE;
        const float* sW = sX + GTILE;
        #pragma unroll
        for (int ks = 0; ks < 4; ks++) {
            int kc = ks*8 + t;
            u32 a[4][4];
            #pragma unroll
            for (int mt = 0; mt < 4; mt++) {
                int r = wm0 + mt*16 + g;
                a[mt][0] = __float_as_uint(sX[r*TSTR     + kc]);
                a[mt][1] = __float_as_uint(sX[(r+8)*TSTR + kc]);
                a[mt][2] = __float_as_uint(sX[r*TSTR     + kc + 4]);
                a[mt][3] = __float_as_uint(sX[(r+8)*TSTR + kc + 4]);
            }
            u32 bb[4][2];
            #pragma unroll
            for (int nt = 0; nt < 4; nt++) {
                int r = wn0 + nt*8 + g;
                bb[nt][0] = __float_as_uint(sW[r*TSTR + kc]);
                bb[nt][1] = __float_as_uint(sW[r*TSTR + kc + 4]);
            }
            #pragma unroll
            for (int mt = 0; mt < 4; mt++)
                #pragma unroll
                for (int nt = 0; nt < 4; nt++)
                    mma_tf32(acc[mt][nt], a[mt], bb[nt]);
        }
        __syncthreads();

        int k2 = (it + 2) << 5;
        if (k2 < K) issue_tile(it & 1, k2);
        asm volatile("cp.async.commit_group;" ::: "memory");
    }

    #pragma unroll
    for (int mt = 0; mt < 4; mt++) {
        #pragma unroll
        for (int nt = 0; nt < 4; nt++) {
            int n = n0 + wn0 + nt*8 + 2*t;
            if (PAD && n >= Nout) continue;
            #pragma unroll
            for (int half = 0; half < 2; half++) {
                int m = m0 + wm0 + mt*16 + g + half*8;
                float v0 = acc[mt][nt][half*2 + 0];
                float v1 = acc[mt][nt][half*2 + 1];
                if (bias) { v0 += bias[n]; v1 += bias[n+1]; }
                if (act)  { v0 *= normcdff(v0); v1 *= normcdff(v1); }
                if (res)  { v0 += res[(size_t)m*Nout + n];
                            v1 += res[(size_t)m*Nout + n + 1]; }
                if (RND)  { v0 = tf32r(v0); v1 = tf32r(v1); }
                *(float2*)(Y + (size_t)m*Nout + n) = make_float2(v0, v1);
            }
        }
    }
}

// ---------------------------------------------------------------------------
// Flash attention v2 (tf32 mma, online softmax in registers).
// Block = (b, h, 128-query tile), 8 warps; warp owns 16 query rows.
// 64-key chunks, K/V register-prefetched one chunk ahead.
// Output tf32-rounded (feeds proj GEMM only).
// ---------------------------------------------------------------------------
#define FQT  128
#define FKC  64
#define QSTR 36
#define VSTR 68
#define FSMEM ((FQT*QSTR + FKC*QSTR + 32*VSTR)*4)

__global__ __launch_bounds__(256) void flash_tc(
    const float* __restrict__ qkv, float* __restrict__ out)
{
    extern __shared__ float sm[];
    float* q_s = sm;                    // FQT x 36
    float* k_s = sm + FQT*QSTR;         // FKC x 36
    float* v_s = k_s + FKC*QSTR;        // 32 x 68 (transposed: [dh][key])

    int tid  = threadIdx.x;
    int warp = tid >> 5, lane = tid & 31;
    int g = lane >> 2, t = lane & 3;
    int b = blockIdx.z, h = blockIdx.y;
    int q0 = blockIdx.x * FQT;
    const float* qb = qkv + (size_t)b*N_*768 + h*32;
    const float scale = 0.17677669529663687f;   // 32^-0.5 (folded into Q)

    for (int ii = tid; ii < FQT*8; ii += 256) {
        int r = ii >> 3, c4q = (ii & 7) << 2;
        float4 v = *(const float4*)(qb + (size_t)(q0+r)*768 + c4q);
        q_s[r*QSTR + c4q + 0] = tf32r(v.x*scale);
        q_s[r*QSTR + c4q + 1] = tf32r(v.y*scale);
        q_s[r*QSTR + c4q + 2] = tf32r(v.z*scale);
        q_s[r*QSTR + c4q + 3] = tf32r(v.w*scale);
    }

    int row0 = warp * 16;
    float oa[4][4];
    #pragma unroll
    for (int nt = 0; nt < 4; nt++)
        #pragma unroll
        for (int c = 0; c < 4; c++) oa[nt][c] = 0.f;
    float mr0 = -1e30f, mr1 = -1e30f, lr0 = 0.f, lr1 = 0.f;

    int src_lo = (lane & ~3) | (t >> 1);
    int src_hi = src_lo | 2;

    int rA = tid >> 3, rB = rA + 32;
    int c4 = (tid & 7) << 2;

    float4 kfA = *(const float4*)(qb + (size_t)rA*768 + 256 + c4);
    float4 kfB = *(const float4*)(qb + (size_t)rB*768 + 256 + c4);
    float4 vfA = *(const float4*)(qb + (size_t)rA*768 + 512 + c4);
    float4 vfB = *(const float4*)(qb + (size_t)rB*768 + 512 + c4);

    for (int kt = 0; kt < N_; kt += FKC) {
        __syncthreads();
        k_s[rA*QSTR + c4 + 0] = tf32r(kfA.x);
        k_s[rA*QSTR + c4 + 1] = tf32r(kfA.y);
        k_s[rA*QSTR + c4 + 2] = tf32r(kfA.z);
        k_s[rA*QSTR + c4 + 3] = tf32r(kfA.w);
        k_s[rB*QSTR + c4 + 0] = tf32r(kfB.x);
        k_s[rB*QSTR + c4 + 1] = tf32r(kfB.y);
        k_s[rB*QSTR + c4 + 2] = tf32r(kfB.z);
        k_s[rB*QSTR + c4 + 3] = tf32r(kfB.w);
        v_s[(c4+0)*VSTR + rA] = tf32r(vfA.x);
        v_s[(c4+1)*VSTR + rA] = tf32r(vfA.y);
        v_s[(c4+2)*VSTR + rA] = tf32r(vfA.z);
        v_s[(c4+3)*VSTR + rA] = tf32r(vfA.w);
        v_s[(c4+0)*VSTR + rB] = tf32r(vfB.x);
        v_s[(c4+1)*VSTR + rB] = tf32r(vfB.y);
        v_s[(c4+2)*VSTR + rB] = tf32r(vfB.z);
        v_s[(c4+3)*VSTR + rB] = tf32r(vfB.w);
        __syncthreads();

        int ktn = kt + FKC;
        if (ktn < N_) {
            kfA = *(const float4*)(qb + (size_t)(ktn+rA)*768 + 256 + c4);
            kfB = *(const float4*)(qb + (size_t)(ktn+rB)*768 + 256 + c4);
            vfA = *(const float4*)(qb + (size_t)(ktn+rA)*768 + 512 + c4);
            vfB = *(const float4*)(qb + (size_t)(ktn+rB)*768 + 512 + c4);
        }

        float s[8][4];
        #pragma unroll
        for (int nt = 0; nt < 8; nt++)
            #pragma unroll
            for (int c = 0; c < 4; c++) s[nt][c] = 0.f;

        #pragma unroll
        for (int ks = 0; ks < 4; ks++) {
            int kc = ks*8 + t;
            u32 a[4];
            a[0] = __float_as_uint(q_s[(row0+g)*QSTR   + kc]);
            a[1] = __float_as_uint(q_s[(row0+8+g)*QSTR + kc]);
            a[2] = __float_as_uint(q_s[(row0+g)*QSTR   + kc + 4]);
            a[3] = __float_as_uint(q_s[(row0+8+g)*QSTR + kc + 4]);
            u32 bb[8][2];
            #pragma unroll
            for (int nt = 0; nt < 8; nt++) {
                int rr = nt*8 + g;
                bb[nt][0] = __float_as_uint(k_s[rr*QSTR + kc]);
                bb[nt][1] = __float_as_uint(k_s[rr*QSTR + kc + 4]);
            }
            #pragma unroll
            for (int nt = 0; nt < 8; nt++)
                mma_tf32(s[nt], a, bb[nt]);
        }

        {
            float m0 = -1e30f, m1 = -1e30f;
            #pragma unroll
            for (int nt = 0; nt < 8; nt++) {
                m0 = fmaxf(m0, fmaxf(s[nt][0], s[nt][1]));
                m1 = fmaxf(m1, fmaxf(s[nt][2], s[nt][3]));
            }
            #pragma unroll
            for (int o = 1; o <= 2; o <<= 1) {
                m0 = fmaxf(m0, __shfl_xor_sync(0xffffffffu, m0, o));
                m1 = fmaxf(m1, __shfl_xor_sync(0xffffffffu, m1, o));
            }
            float mn0 = fmaxf(mr0, m0);
            float mn1 = fmaxf(mr1, m1);
            float sf0 = __expf(mr0 - mn0);
            float sf1 = __expf(mr1 - mn1);
            mr0 = mn0; mr1 = mn1;
            float ls0 = 0.f, ls1 = 0.f;
            #pragma unroll
            for (int nt = 0; nt < 8; nt++) {
                float e0 = __expf(s[nt][0] - mn0);
                float e1 = __expf(s[nt][1] - mn0);
                float e2 = __expf(s[nt][2] - mn1);
                float e3 = __expf(s[nt][3] - mn1);
                ls0 += e0 + e1;  ls1 += e2 + e3;
                s[nt][0] = tf32r(e0);  s[nt][1] = tf32r(e1);
                s[nt][2] = tf32r(e2);  s[nt][3] = tf32r(e3);
            }
            #pragma unroll
            for (int o = 1; o <= 2; o <<= 1) {
                ls0 += __shfl_xor_sync(0xffffffffu, ls0, o);
                ls1 += __shfl_xor_sync(0xffffffffu, ls1, o);
            }
            lr0 = lr0*sf0 + ls0;
            lr1 = lr1*sf1 + ls1;
            #pragma unroll
            for (int nt = 0; nt < 4; nt++) {
                oa[nt][0] *= sf0;  oa[nt][1] *= sf0;
                oa[nt][2] *= sf1;  oa[nt][3] *= sf1;
            }
        }

        #pragma unroll
        for (int k8 = 0; k8 < 8; k8++) {
            float y00 = __shfl_sync(0xffffffffu, s[k8][0], src_lo);
            float y01 = __shfl_sync(0xffffffffu, s[k8][1], src_lo);
            float y10 = __shfl_sync(0xffffffffu, s[k8][0], src_hi);
            float y11 = __shfl_sync(0xffffffffu, s[k8][1], src_hi);
            float z00 = __shfl_sync(0xffffffffu, s[k8][2], src_lo);
            float z01 = __shfl_sync(0xffffffffu, s[k8][3], src_lo);
            float z10 = __shfl_sync(0xffffffffu, s[k8][2], src_hi);
            float z11 = __shfl_sync(0xffffffffu, s[k8][3], src_hi);
            u32 a[4];
            a[0] = __float_as_uint((t & 1) ? y01 : y00);
            a[2] = __float_as_uint((t & 1) ? y11 : y10);
            a[1] = __float_as_uint((t & 1) ? z01 : z00);
            a[3] = __float_as_uint((t & 1) ? z11 : z10);
            u32 bb[4][2];
            #pragma unroll
            for (int nt = 0; nt < 4; nt++) {
                int d = nt*8 + g;
                bb[nt][0] = __float_as_uint(v_s[d*VSTR + k8*8 + t]);
                bb[nt][1] = __float_as_uint(v_s[d*VSTR + k8*8 + t + 4]);
            }
            #pragma unroll
            for (int nt = 0; nt < 4; nt++)
                mma_tf32(oa[nt], a, bb[nt]);
        }
    }

    float i0 = 1.f / lr0;
    float i1 = 1.f / lr1;
    int r = q0 + row0 + g;
    #pragma unroll
    for (int nt = 0; nt < 4; nt++) {
        int col = h*32 + nt*8 + 2*t;
        *(float2*)(out + ((size_t)b*N_ + r)*C_ + col) =
            make_float2(tf32r(oa[nt][0]*i0), tf32r(oa[nt][1]*i0));
        *(float2*)(out + ((size_t)b*N_ + r + 8)*C_ + col) =
            make_float2(tf32r(oa[nt][2]*i1), tf32r(oa[nt][3]*i1));
    }
}

// ---------------------------------------------------------------------------
// Deformable gather: one warp per (b, n, head); lane = channel d.
// Output tf32-rounded (feeds oproj GEMM only).
// ---------------------------------------------------------------------------
__global__ __launch_bounds__(128) void deform_kernel(
    const float* __restrict__ ref, const float* __restrict__ off,
    const float* __restrict__ awl, const float* __restrict__ vp,
    float* __restrict__ out)
{
    int u = (blockIdx.x << 2) + (threadIdx.x >> 5);
    int lane = threadIdx.x & 31;
    int h  = u & 7;
    int bn = u >> 3;
    int b  = bn >> 10;

    float rx = ref[(size_t)bn*2 + 0]*32.f - 0.5f;
    float ry = ref[(size_t)bn*2 + 1]*32.f - 0.5f;
    const float* offp = off + (size_t)bn*64 + h*8;
    const float* awp  = awl + (size_t)bn*32 + h*4;

    float a0 = awp[0], a1 = awp[1], a2 = awp[2], a3 = awp[3];
    float mx = fmaxf(fmaxf(a0,a1), fmaxf(a2,a3));
    float e0 = __expf(a0-mx), e1 = __expf(a1-mx), e2 = __expf(a2-mx), e3 = __expf(a3-mx);
    float inv = 1.f/(e0+e1+e2+e3);
    float aw4[4] = {e0*inv, e1*inv, e2*inv, e3*inv};

    const float* vb = vp + (size_t)b*N_*C_ + h*32 + lane;
    float acc = 0.f;
    #pragma unroll
    for (int p = 0; p < 4; p++) {
        float gx = rx + offp[p*2+0];
        float gy = ry + offp[p*2+1];
        float x0f = floorf(gx), y0f = floorf(gy);
        float lx = gx - x0f, ly = gy - y0f;
        int x0 = (int)x0f, y0 = (int)y0f;
        float s = 0.f;
        #pragma unroll
        for (int cy = 0; cy < 2; cy++) {
            int yi = y0 + cy;
            float wy = cy ? ly : (1.f - ly);
            bool vy = (yi >= 0) && (yi < 32);
            int yc = min(max(yi, 0), 31);
            #pragma unroll
            for (int cx = 0; cx < 2; cx++) {
                int xi = x0 + cx;
                float wx = cx ? lx : (1.f - lx);
                bool vx = (xi >= 0) && (xi < 32);
                int xc = min(max(xi, 0), 31);
                float val = (vx && vy) ? vb[(size_t)(yc*32 + xc)*C_] : 0.f;
                s = fmaf(val, wx*wy, s);
            }
        }
        acc = fmaf(aw4[p], s, acc);
    }
    out[(size_t)bn*C_ + h*32 + lane] = tf32r(acc);
}

// ---------------------------------------------------------------------------
// Launch
// ---------------------------------------------------------------------------
extern "C" void kernel_launch(void* const* d_in, const int* in_sizes, int n_in,
                              void* d_out, int out_size)
{
    const float* x       = (const float*)d_in[0];
    const float* ref     = (const float*)d_in[1];
    const float* value   = (const float*)d_in[2];
    const float* ln1w    = (const float*)d_in[3];
    const float* ln1b    = (const float*)d_in[4];
    const float* ln2w    = (const float*)d_in[5];
    const float* ln2b    = (const float*)d_in[6];
    const float* ln3w    = (const float*)d_in[7];
    const float* ln3b    = (const float*)d_in[8];
    const float* qkv_w   = (const float*)d_in[9];
    const float* proj_w  = (const float*)d_in[10];
    const float* proj_b  = (const float*)d_in[11];
    const float* off_w   = (const float*)d_in[12];
    const float* off_b   = (const float*)d_in[13];
    const float* aw_w    = (const float*)d_in[14];
    const float* aw_b    = (const float*)d_in[15];
    const float* vproj_w = (const float*)d_in[16];
    const float* vproj_b = (const float*)d_in[17];
    const float* oproj_w = (const float*)d_in[18];
    const float* oproj_b = (const float*)d_in[19];
    const float* fc1_w   = (const float*)d_in[20];
    const float* fc1_b   = (const float*)d_in[21];
    const float* fc2_w   = (const float*)d_in[22];
    const float* fc2_b   = (const float*)d_in[23];
    float* out = (float*)d_out;

    float *y, *qkvb, *tmp, *x2, *offb, *awb, *vpb, *h1;
    cudaGetSymbolAddress((void**)&y,    g_y);
    cudaGetSymbolAddress((void**)&qkvb, g_qkv);
    cudaGetSymbolAddress((void**)&tmp,  g_tmp);
    cudaGetSymbolAddress((void**)&x2,   g_x2);
    cudaGetSymbolAddress((void**)&offb, g_off);
    cudaGetSymbolAddress((void**)&awb,  g_awl);
    cudaGetSymbolAddress((void**)&vpb,  g_vp);
    cudaGetSymbolAddress((void**)&h1,   g_h1);

    cudaFuncSetAttribute(flash_tc,
        cudaFuncAttributeMaxDynamicSharedMemorySize, FSMEM);
    cudaFuncSetAttribute(gemm_tc_t<0,0>,
        cudaFuncAttributeMaxDynamicSharedMemorySize, GSMEM);
    cudaFuncSetAttribute(gemm_tc_t<1,0>,
        cudaFuncAttributeMaxDynamicSharedMemorySize, GSMEM);
    cudaFuncSetAttribute(gemm_tc_t<0,1>,
        cudaFuncAttributeMaxDynamicSharedMemorySize, GSMEM);

    // x1 = x + attn(ln1(x))
    ln_kernel<<<M_, 256>>>(x, ln1w, ln1b, y);
    gemm_tc_t<0,0><<<dim3(6,128), 256, GSMEM>>>(y, qkv_w, nullptr, nullptr, qkvb, M_, 768, 256, 0);
    flash_tc<<<dim3(N_/FQT, NH_, B_), 256, FSMEM>>>(qkvb, tmp);
    gemm_tc_t<0,0><<<dim3(2,128), 256, GSMEM>>>(tmp, proj_w, proj_b, x, x2, M_, 256, 256, 0);

    // x2 = x1 + deform(ln2(x1))
    ln_kernel<<<M_, 256>>>(x2, ln2w, ln2b, y);
    gemm_tc_t<1,0><<<dim3(1,128), 256, GSMEM>>>(y, off_w, off_b, nullptr, offb, M_, 64, 256, 0);
    gemm_tc_t<1,0><<<dim3(1,128), 256, GSMEM>>>(y, aw_w,  aw_b,  nullptr, awb,  M_, 32, 256, 0);
    gemm_tc_t<0,0><<<dim3(2,128), 256, GSMEM>>>(value, vproj_w, vproj_b, nullptr, vpb, M_, 256, 256, 0);
    deform_kernel<<<32768, 128>>>(ref, offb, awb, vpb, tmp);
    gemm_tc_t<0,0><<<dim3(2,128), 256, GSMEM>>>(tmp, oproj_w, oproj_b, x2, x2, M_, 256, 256, 0);

    // out = x2 + fc2(gelu(fc1(ln3(x2))))
    ln_kernel<<<M_, 256>>>(x2, ln3w, ln3b, y);
    gemm_tc_t<0,1><<<dim3(8,128), 256, GSMEM>>>(y, fc1_w, fc1_b, nullptr, h1, M_, 1024, 256, 1);
    gemm_tc_t<0,0><<<dim3(2,128), 256, GSMEM>>>(h1, fc2_w, fc2_b, x2, out, M_, 256, 1024, 0);
}